// round 11
// baseline (speedup 1.0000x reference)
#include <cuda_runtime.h>
#include <cuda_bf16.h>
#include <math.h>
#include <stdint.h>

#define HIDDEN 2048
#define NHEADS 16
#define HDIM 128
#define RDIM 32
#define BATCH 2
#define SEQ 1024
#define CACHEDLEN 1024
#define TOTLEN 2048
#define MTOK (BATCH*SEQ)

// ============================ scratch globals ================================
__device__ __nv_bfloat16 g_qh[(size_t)BATCH * NHEADS * SEQ * HDIM];
__device__ __nv_bfloat16 g_ql[(size_t)BATCH * NHEADS * SEQ * HDIM];
__device__ __nv_bfloat16 g_kh[(size_t)BATCH * NHEADS * TOTLEN * HDIM];
__device__ __nv_bfloat16 g_kl[(size_t)BATCH * NHEADS * TOTLEN * HDIM];
__device__ __nv_bfloat16 g_vth[(size_t)BATCH * NHEADS * HDIM * TOTLEN];  // [bh][d][t]
__device__ __nv_bfloat16 g_vtl[(size_t)BATCH * NHEADS * HDIM * TOTLEN];
__device__ __nv_bfloat16 g_ah[(size_t)MTOK * HIDDEN];
__device__ __nv_bfloat16 g_al[(size_t)MTOK * HIDDEN];
__device__ __nv_bfloat16 g_wqh[(size_t)3 * HIDDEN * HIDDEN];
__device__ __nv_bfloat16 g_wql[(size_t)3 * HIDDEN * HIDDEN];
__device__ __nv_bfloat16 g_wdh[(size_t)HIDDEN * HIDDEN];
__device__ __nv_bfloat16 g_wdl[(size_t)HIDDEN * HIDDEN];
__device__ __nv_bfloat16 g_xh[(size_t)MTOK * HIDDEN];
__device__ __nv_bfloat16 g_xl[(size_t)MTOK * HIDDEN];
__device__ float g_cos[SEQ][16];
__device__ float g_sin[SEQ][16];

// ============================ PTX helpers ====================================
__device__ __forceinline__ uint32_t smem_u32(const void* p) {
    uint32_t a;
    asm("{ .reg .u64 t; cvta.to.shared.u64 t, %1; cvt.u32.u64 %0, t; }" : "=r"(a) : "l"(p));
    return a;
}
#define LDSM4(r0, r1, r2, r3, a) \
    asm volatile("ldmatrix.sync.aligned.m8n8.x4.shared.b16 {%0,%1,%2,%3}, [%4];" \
        : "=r"(r0), "=r"(r1), "=r"(r2), "=r"(r3) : "r"(a))
__device__ __forceinline__ void mma_bf16(float* c, const uint32_t* a, const uint32_t* b) {
    asm volatile("mma.sync.aligned.m16n8k16.row.col.f32.bf16.bf16.f32 "
        "{%0,%1,%2,%3}, {%4,%5,%6,%7}, {%8,%9}, {%0,%1,%2,%3};"
        : "+f"(c[0]), "+f"(c[1]), "+f"(c[2]), "+f"(c[3])
        : "r"(a[0]), "r"(a[1]), "r"(a[2]), "r"(a[3]), "r"(b[0]), "r"(b[1]));
}
__device__ __forceinline__ void cp_async16(uint32_t dst, const void* src) {
    asm volatile("cp.async.cg.shared.global [%0], [%1], 16;" :: "r"(dst), "l"(src));
}
#define CP_COMMIT() asm volatile("cp.async.commit_group;" ::: "memory")
#define CP_WAIT(n)  asm volatile("cp.async.wait_group %0;" :: "n"(n) : "memory")

__device__ __forceinline__ void split2(float v, __nv_bfloat16& h, __nv_bfloat16& l) {
    h = __float2bfloat16(v);
    l = __float2bfloat16(v - __bfloat162float(h));
}

// ====== split-bf16 GEMM body (cp.async double-buffered) ======================
// MODE 0: plain store C = A@B^T + bias.
// MODE 1: QKV epilogue — bias + RoPE + split writes (C = out_fk base).
#define BK 32
#define ASTRIDE 40
#define TILE_BYTES (128 * ASTRIDE * 2)    // 10240
#define STAGE_BYTES (4 * TILE_BYTES)      // 40960
#define G_SMEM (2 * STAGE_BYTES)          // 81920  -> 2 CTAs/SM

template<int MODE> __device__ __forceinline__
void gemm_body(int bx, int by,
               const __nv_bfloat16* __restrict__ Ah,
               const __nv_bfloat16* __restrict__ Al,
               const __nv_bfloat16* __restrict__ Bh,
               const __nv_bfloat16* __restrict__ Bl,
               const float* __restrict__ bias,
               float* __restrict__ C, int M, int N, int K, char* sm)
{
    const uint32_t sb = smem_u32(sm);
    const int t    = threadIdx.x;
    const int lane = t & 31, wid = t >> 5;
    const int wm = wid >> 2, wn = wid & 3;
    const int m_base = wm * 64, n_base = wn * 32;
    const int m0 = by * 128, n0 = bx * 128;

    const int lrowA = lane & 15;
    const int lcolA = ((lane >> 4) & 1) << 3;
    const int gB    = lane >> 3;
    const int lrowB = (lane & 7) + ((gB >> 1) << 3);
    const int lcolB = (gB & 1) << 3;

    const uint32_t oAh = 0 * TILE_BYTES + ((m_base + lrowA) * ASTRIDE + lcolA) * 2;
    const uint32_t oAl = 1 * TILE_BYTES + ((m_base + lrowA) * ASTRIDE + lcolA) * 2;
    const uint32_t oBh = 2 * TILE_BYTES + ((n_base + lrowB) * ASTRIDE + lcolB) * 2;
    const uint32_t oBl = 3 * TILE_BYTES + ((n_base + lrowB) * ASTRIDE + lcolB) * 2;

    const int ldrow = t >> 2;
    const int ldc   = (t & 3) * 8;
    const uint32_t ldst = (ldrow * ASTRIDE + ldc) * 2;

    const __nv_bfloat16* gsrc[4] = {
        Ah + (size_t)m0 * K, Al + (size_t)m0 * K,
        Bh + (size_t)n0 * K, Bl + (size_t)n0 * K };

    float acc[4][4][4];
#pragma unroll
    for (int i = 0; i < 4; i++)
#pragma unroll
        for (int j = 0; j < 4; j++)
#pragma unroll
            for (int l = 0; l < 4; l++) acc[i][j][l] = 0.f;

    const int NK = K / BK;

    {
        uint32_t db = sb;
#pragma unroll
        for (int tile = 0; tile < 4; tile++) {
            const __nv_bfloat16* s = gsrc[tile] + ldc;
#pragma unroll
            for (int l = 0; l < 2; l++)
                cp_async16(db + tile * TILE_BYTES + ldst + l * 64 * ASTRIDE * 2,
                           s + (size_t)(ldrow + l * 64) * K);
        }
        CP_COMMIT();
    }

    for (int kci = 0; kci < NK; kci++) {
        if (kci + 1 < NK) {
            const int kc = (kci + 1) * BK;
            uint32_t db = sb + ((kci + 1) & 1) * STAGE_BYTES;
#pragma unroll
            for (int tile = 0; tile < 4; tile++) {
                const __nv_bfloat16* s = gsrc[tile] + kc + ldc;
#pragma unroll
                for (int l = 0; l < 2; l++)
                    cp_async16(db + tile * TILE_BYTES + ldst + l * 64 * ASTRIDE * 2,
                               s + (size_t)(ldrow + l * 64) * K);
            }
            CP_COMMIT();
            CP_WAIT(1);
        } else {
            CP_WAIT(0);
        }
        __syncthreads();

        const uint32_t stg = sb + (kci & 1) * STAGE_BYTES;
        const uint32_t aAh0 = stg + oAh, aAl0 = stg + oAl;
        const uint32_t aBh0 = stg + oBh, aBl0 = stg + oBl;

#pragma unroll
        for (int ks = 0; ks < BK / 16; ks++) {
            const int k0b = (ks * 16) * 2;
            uint32_t ah[4][4], bh[2][4];
#pragma unroll
            for (int mt = 0; mt < 4; mt++)
                LDSM4(ah[mt][0], ah[mt][1], ah[mt][2], ah[mt][3],
                      aAh0 + mt * 16 * ASTRIDE * 2 + k0b);
#pragma unroll
            for (int nt = 0; nt < 2; nt++)
                LDSM4(bh[nt][0], bh[nt][1], bh[nt][2], bh[nt][3],
                      aBh0 + nt * 16 * ASTRIDE * 2 + k0b);
#pragma unroll
            for (int mt = 0; mt < 4; mt++)
#pragma unroll
                for (int nt = 0; nt < 2; nt++) {
                    mma_bf16(acc[mt][nt * 2 + 0], ah[mt], &bh[nt][0]);
                    mma_bf16(acc[mt][nt * 2 + 1], ah[mt], &bh[nt][2]);
                }
            uint32_t bl[2][4];
#pragma unroll
            for (int nt = 0; nt < 2; nt++)
                LDSM4(bl[nt][0], bl[nt][1], bl[nt][2], bl[nt][3],
                      aBl0 + nt * 16 * ASTRIDE * 2 + k0b);
#pragma unroll
            for (int mt = 0; mt < 4; mt++)
#pragma unroll
                for (int nt = 0; nt < 2; nt++) {
                    mma_bf16(acc[mt][nt * 2 + 0], ah[mt], &bl[nt][0]);
                    mma_bf16(acc[mt][nt * 2 + 1], ah[mt], &bl[nt][2]);
                }
#pragma unroll
            for (int mt = 0; mt < 4; mt++)
                LDSM4(ah[mt][0], ah[mt][1], ah[mt][2], ah[mt][3],
                      aAl0 + mt * 16 * ASTRIDE * 2 + k0b);
#pragma unroll
            for (int mt = 0; mt < 4; mt++)
#pragma unroll
                for (int nt = 0; nt < 2; nt++) {
                    mma_bf16(acc[mt][nt * 2 + 0], ah[mt], &bh[nt][0]);
                    mma_bf16(acc[mt][nt * 2 + 1], ah[mt], &bh[nt][2]);
                }
        }
        __syncthreads();
    }

    // -------- bias (both modes) --------
#pragma unroll
    for (int mt = 0; mt < 4; mt++)
#pragma unroll
        for (int n = 0; n < 4; n++) {
            int c = n0 + n_base + (lane & 3) * 2 + n * 8;
            float b0 = bias[c], b1 = bias[c + 1];
            acc[mt][n][0] += b0; acc[mt][n][1] += b1;
            acc[mt][n][2] += b0; acc[mt][n][3] += b1;
        }

    if (MODE == 0) {
        const int row0 = m0 + m_base + (lane >> 2);
        const int col0 = n0 + n_base + (lane & 3) * 2;
#pragma unroll
        for (int mt = 0; mt < 4; mt++) {
#pragma unroll
            for (int n = 0; n < 4; n++) {
                int r = row0 + mt * 16;
                int c = col0 + n * 8;
                float2 v0 = { acc[mt][n][0], acc[mt][n][1] };
                float2 v1 = { acc[mt][n][2], acc[mt][n][3] };
                *(float2*)(C + (size_t)r * N + c) = v0;
                *(float2*)(C + (size_t)(r + 8) * N + c) = v1;
            }
        }
        return;
    }

    // -------- MODE 1: QKV epilogue --------
    const int b    = m0 >> 10;
    const int head = (n0 >> 7) & 15;
    const int bh   = b * NHEADS + head;

    if (n0 < 4096) {
        // Q or K tile: rope on the rotary warp (n_base == 0)
        if (n_base == 0) {
            const int jb = (lane & 3) * 2;
#pragma unroll
            for (int mt = 0; mt < 4; mt++) {
                int r = m0 + m_base + (lane >> 2) + mt * 16;
                int s0 = r & (SEQ - 1), s1 = (r + 8) & (SEQ - 1);
                float tmp[4][4];
#pragma unroll
                for (int n = 0; n < 4; n++)
#pragma unroll
                    for (int l = 0; l < 4; l++) tmp[n][l] = acc[mt][n][l];
#pragma unroll
                for (int n = 0; n < 4; n++) {
                    float sgn = (n < 2) ? -1.f : 1.f;
#pragma unroll
                    for (int l = 0; l < 4; l++) {
                        int j = jb + (l & 1) + (n & 1) * 8;
                        float cs = (l < 2) ? g_cos[s0][j] : g_cos[s1][j];
                        float sn = (l < 2) ? g_sin[s0][j] : g_sin[s1][j];
                        acc[mt][n][l] = tmp[n][l] * cs + sgn * tmp[n ^ 2][l] * sn;
                    }
                }
            }
        }
        const bool isQ = (n0 < 2048);
#pragma unroll
        for (int mt = 0; mt < 4; mt++) {
            int r = m0 + m_base + (lane >> 2) + mt * 16;
            int s0 = r & (SEQ - 1), s1 = (r + 8) & (SEQ - 1);
#pragma unroll
            for (int n = 0; n < 4; n++) {
                int d = n_base + (lane & 3) * 2 + n * 8;
                float v00 = acc[mt][n][0], v01 = acc[mt][n][1];
                float v10 = acc[mt][n][2], v11 = acc[mt][n][3];
                __nv_bfloat162 h2, l2;
                if (isQ) {
                    size_t o0 = ((size_t)bh * SEQ + s0) * HDIM + d;
                    size_t o1 = ((size_t)bh * SEQ + s1) * HDIM + d;
                    split2(v00, h2.x, l2.x); split2(v01, h2.y, l2.y);
                    *(__nv_bfloat162*)(g_qh + o0) = h2; *(__nv_bfloat162*)(g_ql + o0) = l2;
                    split2(v10, h2.x, l2.x); split2(v11, h2.y, l2.y);
                    *(__nv_bfloat162*)(g_qh + o1) = h2; *(__nv_bfloat162*)(g_ql + o1) = l2;
                } else {
                    size_t o0 = ((size_t)bh * TOTLEN + CACHEDLEN + s0) * HDIM + d;
                    size_t o1 = ((size_t)bh * TOTLEN + CACHEDLEN + s1) * HDIM + d;
                    split2(v00, h2.x, l2.x); split2(v01, h2.y, l2.y);
                    *(__nv_bfloat162*)(g_kh + o0) = h2; *(__nv_bfloat162*)(g_kl + o0) = l2;
                    split2(v10, h2.x, l2.x); split2(v11, h2.y, l2.y);
                    *(__nv_bfloat162*)(g_kh + o1) = h2; *(__nv_bfloat162*)(g_kl + o1) = l2;
                    float2 f0 = { v00, v01 }, f1 = { v10, v11 };
                    *(float2*)(C + o0) = f0;   // C = out_fk base in MODE 1
                    *(float2*)(C + o1) = f1;
                }
            }
        }
    } else {
        // V tile: transpose via smem, split to g_vth/g_vtl [bh][d][t]
        float (*T)[129] = (float(*)[129])sm;
#pragma unroll
        for (int mt = 0; mt < 4; mt++) {
            int rl = m_base + (lane >> 2) + mt * 16;
#pragma unroll
            for (int n = 0; n < 4; n++) {
                int cl = n_base + (lane & 3) * 2 + n * 8;
                T[cl][rl]         = acc[mt][n][0];
                T[cl + 1][rl]     = acc[mt][n][1];
                T[cl][rl + 8]     = acc[mt][n][2];
                T[cl + 1][rl + 8] = acc[mt][n][3];
            }
        }
        __syncthreads();
        const int dd = t >> 1, th = (t & 1) * 64;
        const int sbse = m0 & (SEQ - 1);
        size_t ob = (size_t)bh * HDIM * TOTLEN + (size_t)dd * TOTLEN
                  + CACHEDLEN + sbse + th;
#pragma unroll
        for (int i = 0; i < 64; i += 2) {
            __nv_bfloat162 h2, l2;
            split2(T[dd][th + i],     h2.x, l2.x);
            split2(T[dd][th + i + 1], h2.y, l2.y);
            *(__nv_bfloat162*)(g_vth + ob + i) = h2;
            *(__nv_bfloat162*)(g_vtl + ob + i) = l2;
        }
    }
}

// plain GEMM kernel (dense projection)
__global__ __launch_bounds__(256, 2)
void gemm_mma_split_kernel(const __nv_bfloat16* __restrict__ Ah,
                           const __nv_bfloat16* __restrict__ Al,
                           const __nv_bfloat16* __restrict__ Bh,
                           const __nv_bfloat16* __restrict__ Bl,
                           const float* __restrict__ bias,
                           float* __restrict__ C, int M, int N, int K)
{
    extern __shared__ char sm[];
    gemm_body<0>(blockIdx.x, blockIdx.y, Ah, Al, Bh, Bl, bias, C, M, N, K, sm);
}

// ====== fused QKV GEMM (rope/split epilogue) + side work =====================
#define QKV_GEMM_CTAS 768    // 48 x 16
#define NSIDE 128
#define NJOB_CACHE 4096      // 32 bh x 32 t-tiles x 4 d-tiles
#define NJOB_TOT   8192      // + 4096 W_dense 32x32 tiles

__global__ __launch_bounds__(256, 2)
void qkv_fused_kernel(const __nv_bfloat16* __restrict__ Ah,
                      const __nv_bfloat16* __restrict__ Al,
                      const __nv_bfloat16* __restrict__ Bh,
                      const __nv_bfloat16* __restrict__ Bl,
                      const float* __restrict__ bias,
                      const float* __restrict__ ck,
                      const float* __restrict__ ca,
                      float* __restrict__ out_fk,
                      float* __restrict__ out_na,
                      const float* __restrict__ Wd)
{
    extern __shared__ char sm[];
    const int gx = blockIdx.x;
    if (gx < QKV_GEMM_CTAS) {
        gemm_body<1>(gx % 48, gx / 48, Ah, Al, Bh, Bl, bias, out_fk,
                     MTOK, 3 * HIDDEN, HIDDEN, sm);
        return;
    }
    // ---------------- side work -------------------------------------------
    float (*s)[33] = (float(*)[33])sm;
    const int tx = threadIdx.x & 31, ty = threadIdx.x >> 5;
    for (int job = gx - QKV_GEMM_CTAS; job < NJOB_TOT; job += NSIDE) {
        if (job < NJOB_CACHE) {
            const int dt = job & 3, tt = (job >> 2) & 31, bh = job >> 7;
            const int t0 = tt * 32, d0 = dt * 32;
#pragma unroll
            for (int i = 0; i < 32; i += 8) {
                int row = t0 + ty + i;
                size_t si = ((size_t)bh * CACHEDLEN + row) * HDIM + d0 + tx;
                size_t di = ((size_t)bh * TOTLEN + row) * HDIM + d0 + tx;
                float v = ck[si];
                out_fk[di] = v;
                __nv_bfloat16 h, l; split2(v, h, l);
                g_kh[di] = h; g_kl[di] = l;
            }
#pragma unroll
            for (int i = 0; i < 32; i += 8) {
                int row = t0 + ty + i;
                size_t si = ((size_t)bh * CACHEDLEN + row) * HDIM + d0 + tx;
                float v = ca[si];
                out_na[((size_t)bh * TOTLEN + row) * HDIM + d0 + tx] = v;
                s[ty + i][tx] = v;
            }
            __syncthreads();
#pragma unroll
            for (int i = 0; i < 32; i += 8) {
                float v = s[tx][ty + i];
                size_t o = (size_t)bh * HDIM * TOTLEN
                         + (size_t)(d0 + ty + i) * TOTLEN + t0 + tx;
                __nv_bfloat16 h, l; split2(v, h, l);
                g_vth[o] = h; g_vtl[o] = l;
            }
            __syncthreads();
        } else {
            const int j2 = job - NJOB_CACHE;
            const int n0 = (j2 & 63) * 32, k0 = (j2 >> 6) * 32;
#pragma unroll
            for (int i = 0; i < 32; i += 8)
                s[ty + i][tx] = Wd[(size_t)(k0 + ty + i) * HIDDEN + n0 + tx];
            __syncthreads();
#pragma unroll
            for (int i = 0; i < 32; i += 8) {
                float v = s[tx][ty + i];
                size_t o = (size_t)(n0 + ty + i) * HIDDEN + k0 + tx;
                __nv_bfloat16 h, l; split2(v, h, l);
                g_wdh[o] = h; g_wdl[o] = l;
            }
            __syncthreads();
        }
    }
}

// ====== pre kernel: conv_split(hidden) || W_qkv split || rope tables =========
#define PRE_SPLIT_CTAS 1024
#define PRE_CTAS 2048
#define NJOB_WQ 12288        // 192 n-tiles x 64 k-tiles

__global__ void pre_kernel(const float4* __restrict__ hidden,
                           __nv_bfloat162* __restrict__ oh,
                           __nv_bfloat162* __restrict__ ol,
                           const float* __restrict__ Wq)
{
    __shared__ float s[32][33];
    if (blockIdx.x == PRE_CTAS) {
        // rope tables (fp64-accurate)
        for (int i = threadIdx.x; i < SEQ * 16; i += 256) {
            int ss = i >> 4, j = i & 15;
            double ang = (double)(CACHEDLEN + ss)
                       * exp(-(double)j * (1.0 / 16.0) * 9.210340371976184);
            g_cos[ss][j] = (float)cos(ang);
            g_sin[ss][j] = (float)sin(ang);
        }
        return;
    }
    if (blockIdx.x < PRE_SPLIT_CTAS) {
        int base = blockIdx.x * 256 + threadIdx.x;
#pragma unroll
        for (int l = 0; l < 4; l++) {
            int i = base + l * (PRE_SPLIT_CTAS * 256);
            float4 v = hidden[i];
            __nv_bfloat162 p, q;
            split2(v.x, p.x, q.x); split2(v.y, p.y, q.y);
            oh[i * 2 + 0] = p; ol[i * 2 + 0] = q;
            split2(v.z, p.x, q.x); split2(v.w, p.y, q.y);
            oh[i * 2 + 1] = p; ol[i * 2 + 1] = q;
        }
        return;
    }
    const int tx = threadIdx.x & 31, ty = threadIdx.x >> 5;
    for (int job = blockIdx.x - PRE_SPLIT_CTAS; job < NJOB_WQ;
         job += PRE_CTAS - PRE_SPLIT_CTAS) {
        const int n0 = (job % 192) * 32, k0 = (job / 192) * 32;
#pragma unroll
        for (int i = 0; i < 32; i += 8)
            s[ty + i][tx] = Wq[(size_t)(k0 + ty + i) * (3 * HIDDEN) + n0 + tx];
        __syncthreads();
#pragma unroll
        for (int i = 0; i < 32; i += 8) {
            float v = s[tx][ty + i];
            size_t o = (size_t)(n0 + ty + i) * HIDDEN + k0 + tx;
            __nv_bfloat16 h, l; split2(v, h, l);
            g_wqh[o] = h; g_wql[o] = l;
        }
        __syncthreads();
    }
}

// ==== tensor-core flash attention (split-bf16, cp.async, Q-hi in regs) =======
#define ATT_KV0   34816
#define ATT_KVST  71680
#define ATT_SMEM  214784

__device__ __forceinline__
void attn_prefetch(uint32_t stg, int bh, int kv0, int t)
{
    const __nv_bfloat16* Kgh = g_kh + ((size_t)bh * TOTLEN + kv0) * HDIM;
    const __nv_bfloat16* Kgl = g_kl + ((size_t)bh * TOTLEN + kv0) * HDIM;
    const __nv_bfloat16* Vgh = g_vth + (size_t)bh * HDIM * TOTLEN + kv0;
    const __nv_bfloat16* Vgl = g_vtl + (size_t)bh * HDIM * TOTLEN + kv0;
#pragma unroll
    for (int l = 0; l < 4; l++) {
        int idx = t + l * 256;
        int row = idx >> 4, c8 = (idx & 15) * 8;
        cp_async16(stg + (row * 136 + c8) * 2, Kgh + (size_t)row * HDIM + c8);
        cp_async16(stg + 17408 + (row * 136 + c8) * 2, Kgl + (size_t)row * HDIM + c8);
        int vrow = idx >> 3, vc8 = (idx & 7) * 8;
        cp_async16(stg + 34816 + (vrow * 72 + vc8) * 2, Vgh + (size_t)vrow * TOTLEN + vc8);
        cp_async16(stg + 53248 + (vrow * 72 + vc8) * 2, Vgl + (size_t)vrow * TOTLEN + vc8);
    }
}

__global__ __launch_bounds__(256)
void attn_mma_kernel(float* __restrict__ out_na)
{
    extern __shared__ char sm[];
    float* Ss = (float*)(sm + 178176);
    __nv_bfloat16* Phb = (__nv_bfloat16*)(sm + 195584);
    __nv_bfloat16* Plb = (__nv_bfloat16*)(sm + 204800);
    float* rm = (float*)(sm + 214016);
    float* rl = rm + 64;
    float* rc = rm + 128;

    const uint32_t sb  = smem_u32(sm);
    const uint32_t sQh = sb, sQl = sb + 17408;
    const uint32_t sPh = sb + 195584, sPl = sb + 204800;

    const int qt = blockIdx.x;
    const int bh = blockIdx.y;
    const int q0 = qt * 64;
    const int t = threadIdx.x, lane = t & 31, wid = t >> 5;
    const int wm = wid >> 2, wn = wid & 3;
    const int m_base = wm * 32;

    const int n_kv = 17 + qt;

    attn_prefetch(sb + ATT_KV0, bh, 0, t);
    CP_COMMIT();
    {
        const __nv_bfloat16* Qgh = g_qh + ((size_t)bh * SEQ + q0) * HDIM;
        const __nv_bfloat16* Qgl = g_ql + ((size_t)bh * SEQ + q0) * HDIM;
#pragma unroll
        for (int l = 0; l < 4; l++) {
            int idx = t + l * 256;
            int row = idx >> 4, c8 = (idx & 15) * 8;
            *(uint4*)(sm + (row * 136 + c8) * 2) = *(const uint4*)(Qgh + (size_t)row * HDIM + c8);
            *(uint4*)(sm + 17408 + (row * 136 + c8) * 2) = *(const uint4*)(Qgl + (size_t)row * HDIM + c8);
        }
    }
    if (t < 64) { rm[t] = -1e30f; rl[t] = 0.f; }
    __syncthreads();

    const int lrA = lane & 15, lcA = ((lane >> 4) & 1) << 3;
    const int gB = lane >> 3;
    const int lrB = (lane & 7) + ((gB >> 1) << 3), lcB = (gB & 1) << 3;

    // hoist Q-hi fragments into registers (reused every KV tile)
    uint32_t qfh0[8][4], qfh1[8][4];
#pragma unroll
    for (int ks = 0; ks < 8; ks++) {
        LDSM4(qfh0[ks][0], qfh0[ks][1], qfh0[ks][2], qfh0[ks][3],
              sQh + ((m_base + lrA) * 136 + lcA) * 2 + ks * 32);
        LDSM4(qfh1[ks][0], qfh1[ks][1], qfh1[ks][2], qfh1[ks][3],
              sQh + ((m_base + 16 + lrA) * 136 + lcA) * 2 + ks * 32);
    }

    float oacc[2][4][4];
#pragma unroll
    for (int i = 0; i < 2; i++)
#pragma unroll
        for (int j = 0; j < 4; j++)
#pragma unroll
            for (int l = 0; l < 4; l++) oacc[i][j][l] = 0.f;

    for (int kt = 0; kt < n_kv; kt++) {
        const int kv0 = kt * 64;
        if (kt + 1 < n_kv) {
            attn_prefetch(sb + ATT_KV0 + ((kt + 1) & 1) * ATT_KVST, bh, kv0 + 64, t);
            CP_COMMIT();
            CP_WAIT(1);
        } else {
            CP_WAIT(0);
        }
        __syncthreads();

        const uint32_t sKV = sb + ATT_KV0 + (kt & 1) * ATT_KVST;
        const uint32_t sKh = sKV, sKl = sKV + 17408;
        const uint32_t sVh = sKV + 34816, sVl = sKV + 53248;

        float sa[2][2][4];
#pragma unroll
        for (int i = 0; i < 2; i++)
#pragma unroll
            for (int j = 0; j < 2; j++)
#pragma unroll
                for (int l = 0; l < 4; l++) sa[i][j][l] = 0.f;

#pragma unroll
        for (int ks = 0; ks < 8; ks++) {
            const int k0b = ks * 32;
            uint32_t qf0[4], qf1[4], kh[4], kl[4];
            LDSM4(kh[0], kh[1], kh[2], kh[3],
                  sKh + ((wn * 16 + lrB) * 136 + lcB) * 2 + k0b);
            mma_bf16(sa[0][0], qfh0[ks], &kh[0]); mma_bf16(sa[0][1], qfh0[ks], &kh[2]);
            mma_bf16(sa[1][0], qfh1[ks], &kh[0]); mma_bf16(sa[1][1], qfh1[ks], &kh[2]);
            LDSM4(kl[0], kl[1], kl[2], kl[3],
                  sKl + ((wn * 16 + lrB) * 136 + lcB) * 2 + k0b);
            mma_bf16(sa[0][0], qfh0[ks], &kl[0]); mma_bf16(sa[0][1], qfh0[ks], &kl[2]);
            mma_bf16(sa[1][0], qfh1[ks], &kl[0]); mma_bf16(sa[1][1], qfh1[ks], &kl[2]);
            LDSM4(qf0[0], qf0[1], qf0[2], qf0[3],
                  sQl + ((m_base + lrA) * 136 + lcA) * 2 + k0b);
            LDSM4(qf1[0], qf1[1], qf1[2], qf1[3],
                  sQl + ((m_base + 16 + lrA) * 136 + lcA) * 2 + k0b);
            mma_bf16(sa[0][0], qf0, &kh[0]); mma_bf16(sa[0][1], qf0, &kh[2]);
            mma_bf16(sa[1][0], qf1, &kh[0]); mma_bf16(sa[1][1], qf1, &kh[2]);
        }
        {
            const float scale = 0.088388347648318447f;
#pragma unroll
            for (int mt = 0; mt < 2; mt++) {
                int r0 = m_base + mt * 16 + (lane >> 2);
                int lim0 = CACHEDLEN + q0 + r0;
#pragma unroll
                for (int nt = 0; nt < 2; nt++) {
                    int c = wn * 16 + nt * 8 + (lane & 3) * 2;
                    int jg = kv0 + c;
                    Ss[r0 * 68 + c]           = (jg     <= lim0)     ? sa[mt][nt][0] * scale : -1e30f;
                    Ss[r0 * 68 + c + 1]       = (jg + 1 <= lim0)     ? sa[mt][nt][1] * scale : -1e30f;
                    Ss[(r0 + 8) * 68 + c]     = (jg     <= lim0 + 8) ? sa[mt][nt][2] * scale : -1e30f;
                    Ss[(r0 + 8) * 68 + c + 1] = (jg + 1 <= lim0 + 8) ? sa[mt][nt][3] * scale : -1e30f;
                }
            }
        }
        __syncthreads();

        {
            int row = t >> 2, seg = t & 3;
            float vals[16];
            float mx = -1e30f;
#pragma unroll
            for (int j = 0; j < 16; j++) {
                vals[j] = Ss[row * 68 + seg + 4 * j];
                mx = fmaxf(mx, vals[j]);
            }
            mx = fmaxf(mx, __shfl_xor_sync(0xFFFFFFFFu, mx, 1));
            mx = fmaxf(mx, __shfl_xor_sync(0xFFFFFFFFu, mx, 2));
            float mo = rm[row];
            float mxn = fmaxf(mo, mx);
            float sum = 0.f;
#pragma unroll
            for (int j = 0; j < 16; j++) {
                float p = __expf(vals[j] - mxn);
                sum += p;
                __nv_bfloat16 ph = __float2bfloat16(p);
                Phb[row * 72 + seg + 4 * j] = ph;
                Plb[row * 72 + seg + 4 * j] = __float2bfloat16(p - __bfloat162float(ph));
            }
            sum += __shfl_xor_sync(0xFFFFFFFFu, sum, 1);
            sum += __shfl_xor_sync(0xFFFFFFFFu, sum, 2);
            if (seg == 0) {
                float corr = __expf(mo - mxn);
                rl[row] = rl[row] * corr + sum;
                rm[row] = mxn;
                rc[row] = corr;
            }
        }
        __syncthreads();

#pragma unroll
        for (int mt = 0; mt < 2; mt++) {
            float c0 = rc[m_base + mt * 16 + (lane >> 2)];
            float c1 = rc[m_base + mt * 16 + 8 + (lane >> 2)];
#pragma unroll
            for (int nt = 0; nt < 4; nt++) {
                oacc[mt][nt][0] *= c0; oacc[mt][nt][1] *= c0;
                oacc[mt][nt][2] *= c1; oacc[mt][nt][3] *= c1;
            }
        }
#pragma unroll
        for (int ks = 0; ks < 4; ks++) {
            const int k0b = ks * 32;
            uint32_t pf0[4], pf1[4], vh0[4], vh1[4], vx0[4], vx1[4];
            LDSM4(pf0[0], pf0[1], pf0[2], pf0[3],
                  sPh + ((m_base + lrA) * 72 + lcA) * 2 + k0b);
            LDSM4(pf1[0], pf1[1], pf1[2], pf1[3],
                  sPh + ((m_base + 16 + lrA) * 72 + lcA) * 2 + k0b);
            LDSM4(vh0[0], vh0[1], vh0[2], vh0[3],
                  sVh + ((wn * 32 + lrB) * 72 + lcB) * 2 + k0b);
            LDSM4(vh1[0], vh1[1], vh1[2], vh1[3],
                  sVh + ((wn * 32 + 16 + lrB) * 72 + lcB) * 2 + k0b);
            mma_bf16(oacc[0][0], pf0, &vh0[0]); mma_bf16(oacc[0][1], pf0, &vh0[2]);
            mma_bf16(oacc[0][2], pf0, &vh1[0]); mma_bf16(oacc[0][3], pf0, &vh1[2]);
            mma_bf16(oacc[1][0], pf1, &vh0[0]); mma_bf16(oacc[1][1], pf1, &vh0[2]);
            mma_bf16(oacc[1][2], pf1, &vh1[0]); mma_bf16(oacc[1][3], pf1, &vh1[2]);
            LDSM4(vx0[0], vx0[1], vx0[2], vx0[3],
                  sVl + ((wn * 32 + lrB) * 72 + lcB) * 2 + k0b);
            LDSM4(vx1[0], vx1[1], vx1[2], vx1[3],
                  sVl + ((wn * 32 + 16 + lrB) * 72 + lcB) * 2 + k0b);
            mma_bf16(oacc[0][0], pf0, &vx0[0]); mma_bf16(oacc[0][1], pf0, &vx0[2]);
            mma_bf16(oacc[0][2], pf0, &vx1[0]); mma_bf16(oacc[0][3], pf0, &vx1[2]);
            mma_bf16(oacc[1][0], pf1, &vx0[0]); mma_bf16(oacc[1][1], pf1, &vx0[2]);
            mma_bf16(oacc[1][2], pf1, &vx1[0]); mma_bf16(oacc[1][3], pf1, &vx1[2]);
            LDSM4(pf0[0], pf0[1], pf0[2], pf0[3],
                  sPl + ((m_base + lrA) * 72 + lcA) * 2 + k0b);
            LDSM4(pf1[0], pf1[1], pf1[2], pf1[3],
                  sPl + ((m_base + 16 + lrA) * 72 + lcA) * 2 + k0b);
            mma_bf16(oacc[0][0], pf0, &vh0[0]); mma_bf16(oacc[0][1], pf0, &vh0[2]);
            mma_bf16(oacc[0][2], pf0, &vh1[0]); mma_bf16(oacc[0][3], pf0, &vh1[2]);
            mma_bf16(oacc[1][0], pf1, &vh0[0]); mma_bf16(oacc[1][1], pf1, &vh0[2]);
            mma_bf16(oacc[1][2], pf1, &vh1[0]); mma_bf16(oacc[1][3], pf1, &vh1[2]);
        }
        __syncthreads();
    }

    const int b = bh >> 4, h = bh & 15;
#pragma unroll
    for (int mt = 0; mt < 2; mt++) {
        int r0 = m_base + mt * 16 + (lane >> 2);
        int r1 = r0 + 8;
        float i0 = 1.f / rl[r0], i1 = 1.f / rl[r1];
#pragma unroll
        for (int nt = 0; nt < 4; nt++) {
            int c = wn * 32 + nt * 8 + (lane & 3) * 2;
            float o00 = oacc[mt][nt][0] * i0, o01 = oacc[mt][nt][1] * i0;
            float o10 = oacc[mt][nt][2] * i1, o11 = oacc[mt][nt][3] * i1;
            float2 v0 = { o00, o01 }, v1 = { o10, o11 };
            *(float2*)(out_na + ((size_t)bh * TOTLEN + CACHEDLEN + q0 + r0) * HDIM + c) = v0;
            *(float2*)(out_na + ((size_t)bh * TOTLEN + CACHEDLEN + q0 + r1) * HDIM + c) = v1;
            size_t x0 = ((size_t)(b * SEQ + q0 + r0)) * HIDDEN + h * HDIM + c;
            size_t x1 = ((size_t)(b * SEQ + q0 + r1)) * HIDDEN + h * HDIM + c;
            __nv_bfloat162 ph, pl;
            split2(o00, ph.x, pl.x); split2(o01, ph.y, pl.y);
            *(__nv_bfloat162*)(g_xh + x0) = ph;
            *(__nv_bfloat162*)(g_xl + x0) = pl;
            split2(o10, ph.x, pl.x); split2(o11, ph.y, pl.y);
            *(__nv_bfloat162*)(g_xh + x1) = ph;
            *(__nv_bfloat162*)(g_xl + x1) = pl;
        }
    }
}

// ---------------- launch ------------------------------------------------------
extern "C" void kernel_launch(void* const* d_in, const int* in_sizes, int n_in,
                              void* d_out, int out_size)
{
    const float* hidden   = (const float*)d_in[0];
    const float* cached_k = (const float*)d_in[2];
    const float* cached_a = (const float*)d_in[3];
    const float* W_qkv    = (const float*)d_in[4];
    const float* b_qkv    = (const float*)d_in[5];
    const float* W_dense  = (const float*)d_in[6];
    const float* b_dense  = (const float*)d_in[7];

    float* out      = (float*)d_out;
    float* out_main = out;
    float* out_fk   = out + (size_t)BATCH * SEQ * HIDDEN;
    float* out_na   = out_fk + (size_t)BATCH * NHEADS * TOTLEN * HDIM;

    static __nv_bfloat16 *ah_p, *al_p, *wqh_p, *wql_p, *wdh_p, *wdl_p, *xh_p, *xl_p;
    static bool init = false;
    if (!init) {
        cudaGetSymbolAddress((void**)&ah_p,  g_ah);
        cudaGetSymbolAddress((void**)&al_p,  g_al);
        cudaGetSymbolAddress((void**)&wqh_p, g_wqh);
        cudaGetSymbolAddress((void**)&wql_p, g_wql);
        cudaGetSymbolAddress((void**)&wdh_p, g_wdh);
        cudaGetSymbolAddress((void**)&wdl_p, g_wdl);
        cudaGetSymbolAddress((void**)&xh_p,  g_xh);
        cudaGetSymbolAddress((void**)&xl_p,  g_xl);
        cudaFuncSetAttribute(gemm_mma_split_kernel,
                             cudaFuncAttributeMaxDynamicSharedMemorySize, G_SMEM);
        cudaFuncSetAttribute(qkv_fused_kernel,
                             cudaFuncAttributeMaxDynamicSharedMemorySize, G_SMEM);
        cudaFuncSetAttribute(attn_mma_kernel,
                             cudaFuncAttributeMaxDynamicSharedMemorySize, ATT_SMEM);
        init = true;
    }

    // 1. conv_split(hidden) || transpose+split W_qkv || rope tables
    pre_kernel<<<PRE_CTAS + 1, 256>>>(
        (const float4*)hidden, (__nv_bfloat162*)ah_p, (__nv_bfloat162*)al_p, W_qkv);

    // 2. QKV GEMM (fused rope/split/V^T epilogue) + side work
    qkv_fused_kernel<<<QKV_GEMM_CTAS + NSIDE, 256, G_SMEM>>>(
        ah_p, al_p, wqh_p, wql_p, b_qkv,
        cached_k, cached_a, out_fk, out_na, W_dense);

    // 3. tensor-core attention (cp.async double-buffered KV)
    attn_mma_kernel<<<dim3(SEQ / 64, BATCH * NHEADS), 256, ATT_SMEM>>>(out_na);

    // 4. dense projection
    gemm_mma_split_kernel<<<dim3(HIDDEN / 128, MTOK / 128), 256, G_SMEM>>>(
        xh_p, xl_p, wdh_p, wdl_p, b_dense, out_main, MTOK, HIDDEN, HIDDEN);
}

// round 12
// speedup vs baseline: 1.0019x; 1.0019x over previous
#include <cuda_runtime.h>
#include <cuda_bf16.h>
#include <math.h>
#include <stdint.h>

#define HIDDEN 2048
#define NHEADS 16
#define HDIM 128
#define RDIM 32
#define BATCH 2
#define SEQ 1024
#define CACHEDLEN 1024
#define TOTLEN 2048
#define MTOK (BATCH*SEQ)

// ============================ scratch globals ================================
__device__ __nv_bfloat16 g_qh[(size_t)BATCH * NHEADS * SEQ * HDIM];
__device__ __nv_bfloat16 g_ql[(size_t)BATCH * NHEADS * SEQ * HDIM];
__device__ __nv_bfloat16 g_kh[(size_t)BATCH * NHEADS * TOTLEN * HDIM];
__device__ __nv_bfloat16 g_kl[(size_t)BATCH * NHEADS * TOTLEN * HDIM];
__device__ __nv_bfloat16 g_vth[(size_t)BATCH * NHEADS * HDIM * TOTLEN];  // [bh][d][t]
__device__ __nv_bfloat16 g_vtl[(size_t)BATCH * NHEADS * HDIM * TOTLEN];
__device__ __nv_bfloat16 g_ah[(size_t)MTOK * HIDDEN];
__device__ __nv_bfloat16 g_al[(size_t)MTOK * HIDDEN];
__device__ __nv_bfloat16 g_wqh[(size_t)3 * HIDDEN * HIDDEN];
__device__ __nv_bfloat16 g_wql[(size_t)3 * HIDDEN * HIDDEN];
__device__ __nv_bfloat16 g_wdh[(size_t)HIDDEN * HIDDEN];
__device__ __nv_bfloat16 g_wdl[(size_t)HIDDEN * HIDDEN];
__device__ __nv_bfloat16 g_xh[(size_t)MTOK * HIDDEN];
__device__ __nv_bfloat16 g_xl[(size_t)MTOK * HIDDEN];
__device__ float g_cos[SEQ][16];
__device__ float g_sin[SEQ][16];

// ============================ PTX helpers ====================================
__device__ __forceinline__ uint32_t smem_u32(const void* p) {
    uint32_t a;
    asm("{ .reg .u64 t; cvta.to.shared.u64 t, %1; cvt.u32.u64 %0, t; }" : "=r"(a) : "l"(p));
    return a;
}
#define LDSM4(r0, r1, r2, r3, a) \
    asm volatile("ldmatrix.sync.aligned.m8n8.x4.shared.b16 {%0,%1,%2,%3}, [%4];" \
        : "=r"(r0), "=r"(r1), "=r"(r2), "=r"(r3) : "r"(a))
__device__ __forceinline__ void mma_bf16(float* c, const uint32_t* a, const uint32_t* b) {
    asm volatile("mma.sync.aligned.m16n8k16.row.col.f32.bf16.bf16.f32 "
        "{%0,%1,%2,%3}, {%4,%5,%6,%7}, {%8,%9}, {%0,%1,%2,%3};"
        : "+f"(c[0]), "+f"(c[1]), "+f"(c[2]), "+f"(c[3])
        : "r"(a[0]), "r"(a[1]), "r"(a[2]), "r"(a[3]), "r"(b[0]), "r"(b[1]));
}
__device__ __forceinline__ void cp_async16(uint32_t dst, const void* src) {
    asm volatile("cp.async.cg.shared.global [%0], [%1], 16;" :: "r"(dst), "l"(src));
}
#define CP_COMMIT() asm volatile("cp.async.commit_group;" ::: "memory")
#define CP_WAIT(n)  asm volatile("cp.async.wait_group %0;" :: "n"(n) : "memory")

__device__ __forceinline__ void split2(float v, __nv_bfloat16& h, __nv_bfloat16& l) {
    h = __float2bfloat16(v);
    l = __float2bfloat16(v - __bfloat162float(h));
}

// ====== split-bf16 GEMM body (cp.async double-buffered) ======================
// MODE 0: plain store C = A@B^T + bias.
// MODE 1: QKV epilogue — bias + RoPE + split writes (C = out_fk base).
#define BK 32
#define ASTRIDE 40
#define TILE_BYTES (128 * ASTRIDE * 2)    // 10240
#define STAGE_BYTES (4 * TILE_BYTES)      // 40960
#define G_SMEM (2 * STAGE_BYTES)          // 81920  -> 2 CTAs/SM

template<int MODE> __device__ __forceinline__
void gemm_body(int bx, int by,
               const __nv_bfloat16* __restrict__ Ah,
               const __nv_bfloat16* __restrict__ Al,
               const __nv_bfloat16* __restrict__ Bh,
               const __nv_bfloat16* __restrict__ Bl,
               const float* __restrict__ bias,
               float* __restrict__ C, int M, int N, int K, char* sm)
{
    const uint32_t sb = smem_u32(sm);
    const int t    = threadIdx.x;
    const int lane = t & 31, wid = t >> 5;
    const int wm = wid >> 2, wn = wid & 3;
    const int m_base = wm * 64, n_base = wn * 32;
    const int m0 = by * 128, n0 = bx * 128;

    const int lrowA = lane & 15;
    const int lcolA = ((lane >> 4) & 1) << 3;
    const int gB    = lane >> 3;
    const int lrowB = (lane & 7) + ((gB >> 1) << 3);
    const int lcolB = (gB & 1) << 3;

    const uint32_t oAh = 0 * TILE_BYTES + ((m_base + lrowA) * ASTRIDE + lcolA) * 2;
    const uint32_t oAl = 1 * TILE_BYTES + ((m_base + lrowA) * ASTRIDE + lcolA) * 2;
    const uint32_t oBh = 2 * TILE_BYTES + ((n_base + lrowB) * ASTRIDE + lcolB) * 2;
    const uint32_t oBl = 3 * TILE_BYTES + ((n_base + lrowB) * ASTRIDE + lcolB) * 2;

    const int ldrow = t >> 2;
    const int ldc   = (t & 3) * 8;
    const uint32_t ldst = (ldrow * ASTRIDE + ldc) * 2;

    const __nv_bfloat16* gsrc[4] = {
        Ah + (size_t)m0 * K, Al + (size_t)m0 * K,
        Bh + (size_t)n0 * K, Bl + (size_t)n0 * K };

    float acc[4][4][4];
#pragma unroll
    for (int i = 0; i < 4; i++)
#pragma unroll
        for (int j = 0; j < 4; j++)
#pragma unroll
            for (int l = 0; l < 4; l++) acc[i][j][l] = 0.f;

    const int NK = K / BK;

    {
        uint32_t db = sb;
#pragma unroll
        for (int tile = 0; tile < 4; tile++) {
            const __nv_bfloat16* s = gsrc[tile] + ldc;
#pragma unroll
            for (int l = 0; l < 2; l++)
                cp_async16(db + tile * TILE_BYTES + ldst + l * 64 * ASTRIDE * 2,
                           s + (size_t)(ldrow + l * 64) * K);
        }
        CP_COMMIT();
    }

    for (int kci = 0; kci < NK; kci++) {
        if (kci + 1 < NK) {
            const int kc = (kci + 1) * BK;
            uint32_t db = sb + ((kci + 1) & 1) * STAGE_BYTES;
#pragma unroll
            for (int tile = 0; tile < 4; tile++) {
                const __nv_bfloat16* s = gsrc[tile] + kc + ldc;
#pragma unroll
                for (int l = 0; l < 2; l++)
                    cp_async16(db + tile * TILE_BYTES + ldst + l * 64 * ASTRIDE * 2,
                               s + (size_t)(ldrow + l * 64) * K);
            }
            CP_COMMIT();
            CP_WAIT(1);
        } else {
            CP_WAIT(0);
        }
        __syncthreads();

        const uint32_t stg = sb + (kci & 1) * STAGE_BYTES;
        const uint32_t aAh0 = stg + oAh, aAl0 = stg + oAl;
        const uint32_t aBh0 = stg + oBh, aBl0 = stg + oBl;

#pragma unroll
        for (int ks = 0; ks < BK / 16; ks++) {
            const int k0b = (ks * 16) * 2;
            uint32_t ah[4][4], bh[2][4];
#pragma unroll
            for (int mt = 0; mt < 4; mt++)
                LDSM4(ah[mt][0], ah[mt][1], ah[mt][2], ah[mt][3],
                      aAh0 + mt * 16 * ASTRIDE * 2 + k0b);
#pragma unroll
            for (int nt = 0; nt < 2; nt++)
                LDSM4(bh[nt][0], bh[nt][1], bh[nt][2], bh[nt][3],
                      aBh0 + nt * 16 * ASTRIDE * 2 + k0b);
#pragma unroll
            for (int mt = 0; mt < 4; mt++)
#pragma unroll
                for (int nt = 0; nt < 2; nt++) {
                    mma_bf16(acc[mt][nt * 2 + 0], ah[mt], &bh[nt][0]);
                    mma_bf16(acc[mt][nt * 2 + 1], ah[mt], &bh[nt][2]);
                }
            uint32_t bl[2][4];
#pragma unroll
            for (int nt = 0; nt < 2; nt++)
                LDSM4(bl[nt][0], bl[nt][1], bl[nt][2], bl[nt][3],
                      aBl0 + nt * 16 * ASTRIDE * 2 + k0b);
#pragma unroll
            for (int mt = 0; mt < 4; mt++)
#pragma unroll
                for (int nt = 0; nt < 2; nt++) {
                    mma_bf16(acc[mt][nt * 2 + 0], ah[mt], &bl[nt][0]);
                    mma_bf16(acc[mt][nt * 2 + 1], ah[mt], &bl[nt][2]);
                }
#pragma unroll
            for (int mt = 0; mt < 4; mt++)
                LDSM4(ah[mt][0], ah[mt][1], ah[mt][2], ah[mt][3],
                      aAl0 + mt * 16 * ASTRIDE * 2 + k0b);
#pragma unroll
            for (int mt = 0; mt < 4; mt++)
#pragma unroll
                for (int nt = 0; nt < 2; nt++) {
                    mma_bf16(acc[mt][nt * 2 + 0], ah[mt], &bh[nt][0]);
                    mma_bf16(acc[mt][nt * 2 + 1], ah[mt], &bh[nt][2]);
                }
        }
        __syncthreads();
    }

    // -------- bias (both modes) --------
#pragma unroll
    for (int mt = 0; mt < 4; mt++)
#pragma unroll
        for (int n = 0; n < 4; n++) {
            int c = n0 + n_base + (lane & 3) * 2 + n * 8;
            float b0 = bias[c], b1 = bias[c + 1];
            acc[mt][n][0] += b0; acc[mt][n][1] += b1;
            acc[mt][n][2] += b0; acc[mt][n][3] += b1;
        }

    if (MODE == 0) {
        const int row0 = m0 + m_base + (lane >> 2);
        const int col0 = n0 + n_base + (lane & 3) * 2;
#pragma unroll
        for (int mt = 0; mt < 4; mt++) {
#pragma unroll
            for (int n = 0; n < 4; n++) {
                int r = row0 + mt * 16;
                int c = col0 + n * 8;
                float2 v0 = { acc[mt][n][0], acc[mt][n][1] };
                float2 v1 = { acc[mt][n][2], acc[mt][n][3] };
                *(float2*)(C + (size_t)r * N + c) = v0;
                *(float2*)(C + (size_t)(r + 8) * N + c) = v1;
            }
        }
        return;
    }

    // -------- MODE 1: QKV epilogue --------
    const int b    = m0 >> 10;
    const int head = (n0 >> 7) & 15;
    const int bh   = b * NHEADS + head;

    if (n0 < 4096) {
        // Q or K tile: rope on the rotary warp (n_base == 0)
        if (n_base == 0) {
            const int jb = (lane & 3) * 2;
#pragma unroll
            for (int mt = 0; mt < 4; mt++) {
                int r = m0 + m_base + (lane >> 2) + mt * 16;
                int s0 = r & (SEQ - 1), s1 = (r + 8) & (SEQ - 1);
                float tmp[4][4];
#pragma unroll
                for (int n = 0; n < 4; n++)
#pragma unroll
                    for (int l = 0; l < 4; l++) tmp[n][l] = acc[mt][n][l];
#pragma unroll
                for (int n = 0; n < 4; n++) {
                    float sgn = (n < 2) ? -1.f : 1.f;
#pragma unroll
                    for (int l = 0; l < 4; l++) {
                        int j = jb + (l & 1) + (n & 1) * 8;
                        float cs = (l < 2) ? g_cos[s0][j] : g_cos[s1][j];
                        float sn = (l < 2) ? g_sin[s0][j] : g_sin[s1][j];
                        acc[mt][n][l] = tmp[n][l] * cs + sgn * tmp[n ^ 2][l] * sn;
                    }
                }
            }
        }
        const bool isQ = (n0 < 2048);
#pragma unroll
        for (int mt = 0; mt < 4; mt++) {
            int r = m0 + m_base + (lane >> 2) + mt * 16;
            int s0 = r & (SEQ - 1), s1 = (r + 8) & (SEQ - 1);
#pragma unroll
            for (int n = 0; n < 4; n++) {
                int d = n_base + (lane & 3) * 2 + n * 8;
                float v00 = acc[mt][n][0], v01 = acc[mt][n][1];
                float v10 = acc[mt][n][2], v11 = acc[mt][n][3];
                __nv_bfloat162 h2, l2;
                if (isQ) {
                    size_t o0 = ((size_t)bh * SEQ + s0) * HDIM + d;
                    size_t o1 = ((size_t)bh * SEQ + s1) * HDIM + d;
                    split2(v00, h2.x, l2.x); split2(v01, h2.y, l2.y);
                    *(__nv_bfloat162*)(g_qh + o0) = h2; *(__nv_bfloat162*)(g_ql + o0) = l2;
                    split2(v10, h2.x, l2.x); split2(v11, h2.y, l2.y);
                    *(__nv_bfloat162*)(g_qh + o1) = h2; *(__nv_bfloat162*)(g_ql + o1) = l2;
                } else {
                    size_t o0 = ((size_t)bh * TOTLEN + CACHEDLEN + s0) * HDIM + d;
                    size_t o1 = ((size_t)bh * TOTLEN + CACHEDLEN + s1) * HDIM + d;
                    split2(v00, h2.x, l2.x); split2(v01, h2.y, l2.y);
                    *(__nv_bfloat162*)(g_kh + o0) = h2; *(__nv_bfloat162*)(g_kl + o0) = l2;
                    split2(v10, h2.x, l2.x); split2(v11, h2.y, l2.y);
                    *(__nv_bfloat162*)(g_kh + o1) = h2; *(__nv_bfloat162*)(g_kl + o1) = l2;
                    float2 f0 = { v00, v01 }, f1 = { v10, v11 };
                    *(float2*)(C + o0) = f0;   // C = out_fk base in MODE 1
                    *(float2*)(C + o1) = f1;
                }
            }
        }
    } else {
        // V tile: transpose via smem, split to g_vth/g_vtl [bh][d][t]
        float (*T)[129] = (float(*)[129])sm;
#pragma unroll
        for (int mt = 0; mt < 4; mt++) {
            int rl = m_base + (lane >> 2) + mt * 16;
#pragma unroll
            for (int n = 0; n < 4; n++) {
                int cl = n_base + (lane & 3) * 2 + n * 8;
                T[cl][rl]         = acc[mt][n][0];
                T[cl + 1][rl]     = acc[mt][n][1];
                T[cl][rl + 8]     = acc[mt][n][2];
                T[cl + 1][rl + 8] = acc[mt][n][3];
            }
        }
        __syncthreads();
        const int dd = t >> 1, th = (t & 1) * 64;
        const int sbse = m0 & (SEQ - 1);
        size_t ob = (size_t)bh * HDIM * TOTLEN + (size_t)dd * TOTLEN
                  + CACHEDLEN + sbse + th;
#pragma unroll
        for (int i = 0; i < 64; i += 2) {
            __nv_bfloat162 h2, l2;
            split2(T[dd][th + i],     h2.x, l2.x);
            split2(T[dd][th + i + 1], h2.y, l2.y);
            *(__nv_bfloat162*)(g_vth + ob + i) = h2;
            *(__nv_bfloat162*)(g_vtl + ob + i) = l2;
        }
    }
}

// plain GEMM kernel (dense projection)
__global__ __launch_bounds__(256, 2)
void gemm_mma_split_kernel(const __nv_bfloat16* __restrict__ Ah,
                           const __nv_bfloat16* __restrict__ Al,
                           const __nv_bfloat16* __restrict__ Bh,
                           const __nv_bfloat16* __restrict__ Bl,
                           const float* __restrict__ bias,
                           float* __restrict__ C, int M, int N, int K)
{
    extern __shared__ char sm[];
    gemm_body<0>(blockIdx.x, blockIdx.y, Ah, Al, Bh, Bl, bias, C, M, N, K, sm);
}

// ====== fused QKV GEMM (rope/split epilogue) + side work =====================
#define QKV_GEMM_CTAS 768    // 48 x 16
#define NSIDE 128
#define NJOB_CACHE 4096      // 32 bh x 32 t-tiles x 4 d-tiles
#define NJOB_TOT   8192      // + 4096 W_dense 32x32 tiles

__global__ __launch_bounds__(256, 2)
void qkv_fused_kernel(const __nv_bfloat16* __restrict__ Ah,
                      const __nv_bfloat16* __restrict__ Al,
                      const __nv_bfloat16* __restrict__ Bh,
                      const __nv_bfloat16* __restrict__ Bl,
                      const float* __restrict__ bias,
                      const float* __restrict__ ck,
                      const float* __restrict__ ca,
                      float* __restrict__ out_fk,
                      float* __restrict__ out_na,
                      const float* __restrict__ Wd)
{
    extern __shared__ char sm[];
    const int gx = blockIdx.x;
    if (gx < QKV_GEMM_CTAS) {
        gemm_body<1>(gx % 48, gx / 48, Ah, Al, Bh, Bl, bias, out_fk,
                     MTOK, 3 * HIDDEN, HIDDEN, sm);
        return;
    }
    // ---------------- side work -------------------------------------------
    float (*s)[33] = (float(*)[33])sm;
    const int tx = threadIdx.x & 31, ty = threadIdx.x >> 5;
    for (int job = gx - QKV_GEMM_CTAS; job < NJOB_TOT; job += NSIDE) {
        if (job < NJOB_CACHE) {
            const int dt = job & 3, tt = (job >> 2) & 31, bh = job >> 7;
            const int t0 = tt * 32, d0 = dt * 32;
#pragma unroll
            for (int i = 0; i < 32; i += 8) {
                int row = t0 + ty + i;
                size_t si = ((size_t)bh * CACHEDLEN + row) * HDIM + d0 + tx;
                size_t di = ((size_t)bh * TOTLEN + row) * HDIM + d0 + tx;
                float v = ck[si];
                out_fk[di] = v;
                __nv_bfloat16 h, l; split2(v, h, l);
                g_kh[di] = h; g_kl[di] = l;
            }
#pragma unroll
            for (int i = 0; i < 32; i += 8) {
                int row = t0 + ty + i;
                size_t si = ((size_t)bh * CACHEDLEN + row) * HDIM + d0 + tx;
                float v = ca[si];
                out_na[((size_t)bh * TOTLEN + row) * HDIM + d0 + tx] = v;
                s[ty + i][tx] = v;
            }
            __syncthreads();
#pragma unroll
            for (int i = 0; i < 32; i += 8) {
                float v = s[tx][ty + i];
                size_t o = (size_t)bh * HDIM * TOTLEN
                         + (size_t)(d0 + ty + i) * TOTLEN + t0 + tx;
                __nv_bfloat16 h, l; split2(v, h, l);
                g_vth[o] = h; g_vtl[o] = l;
            }
            __syncthreads();
        } else {
            const int j2 = job - NJOB_CACHE;
            const int n0 = (j2 & 63) * 32, k0 = (j2 >> 6) * 32;
#pragma unroll
            for (int i = 0; i < 32; i += 8)
                s[ty + i][tx] = Wd[(size_t)(k0 + ty + i) * HIDDEN + n0 + tx];
            __syncthreads();
#pragma unroll
            for (int i = 0; i < 32; i += 8) {
                float v = s[tx][ty + i];
                size_t o = (size_t)(n0 + ty + i) * HIDDEN + k0 + tx;
                __nv_bfloat16 h, l; split2(v, h, l);
                g_wdh[o] = h; g_wdl[o] = l;
            }
            __syncthreads();
        }
    }
}

// ====== pre kernel: conv_split(hidden) || W_qkv split || rope tables =========
#define PRE_SPLIT_CTAS 1024
#define PRE_CTAS 2048
#define NJOB_WQ 12288        // 192 n-tiles x 64 k-tiles

__global__ void pre_kernel(const float4* __restrict__ hidden,
                           __nv_bfloat162* __restrict__ oh,
                           __nv_bfloat162* __restrict__ ol,
                           const float* __restrict__ Wq)
{
    __shared__ float s[32][33];
    if (blockIdx.x == PRE_CTAS) {
        for (int i = threadIdx.x; i < SEQ * 16; i += 256) {
            int ss = i >> 4, j = i & 15;
            double ang = (double)(CACHEDLEN + ss)
                       * exp(-(double)j * (1.0 / 16.0) * 9.210340371976184);
            g_cos[ss][j] = (float)cos(ang);
            g_sin[ss][j] = (float)sin(ang);
        }
        return;
    }
    if (blockIdx.x < PRE_SPLIT_CTAS) {
        int base = blockIdx.x * 256 + threadIdx.x;
#pragma unroll
        for (int l = 0; l < 4; l++) {
            int i = base + l * (PRE_SPLIT_CTAS * 256);
            float4 v = hidden[i];
            __nv_bfloat162 p, q;
            split2(v.x, p.x, q.x); split2(v.y, p.y, q.y);
            oh[i * 2 + 0] = p; ol[i * 2 + 0] = q;
            split2(v.z, p.x, q.x); split2(v.w, p.y, q.y);
            oh[i * 2 + 1] = p; ol[i * 2 + 1] = q;
        }
        return;
    }
    const int tx = threadIdx.x & 31, ty = threadIdx.x >> 5;
    for (int job = blockIdx.x - PRE_SPLIT_CTAS; job < NJOB_WQ;
         job += PRE_CTAS - PRE_SPLIT_CTAS) {
        const int n0 = (job % 192) * 32, k0 = (job / 192) * 32;
#pragma unroll
        for (int i = 0; i < 32; i += 8)
            s[ty + i][tx] = Wq[(size_t)(k0 + ty + i) * (3 * HIDDEN) + n0 + tx];
        __syncthreads();
#pragma unroll
        for (int i = 0; i < 32; i += 8) {
            float v = s[tx][ty + i];
            size_t o = (size_t)(n0 + ty + i) * HIDDEN + k0 + tx;
            __nv_bfloat16 h, l; split2(v, h, l);
            g_wqh[o] = h; g_wql[o] = l;
        }
        __syncthreads();
    }
}

// ==== tensor-core flash attention (split-bf16, cp.async double-buffered) =====
#define ATT_KV0   34816
#define ATT_KVST  71680
#define ATT_SMEM  214784

__device__ __forceinline__
void attn_prefetch(uint32_t stg, int bh, int kv0, int t)
{
    const __nv_bfloat16* Kgh = g_kh + ((size_t)bh * TOTLEN + kv0) * HDIM;
    const __nv_bfloat16* Kgl = g_kl + ((size_t)bh * TOTLEN + kv0) * HDIM;
    const __nv_bfloat16* Vgh = g_vth + (size_t)bh * HDIM * TOTLEN + kv0;
    const __nv_bfloat16* Vgl = g_vtl + (size_t)bh * HDIM * TOTLEN + kv0;
#pragma unroll
    for (int l = 0; l < 4; l++) {
        int idx = t + l * 256;
        int row = idx >> 4, c8 = (idx & 15) * 8;
        cp_async16(stg + (row * 136 + c8) * 2, Kgh + (size_t)row * HDIM + c8);
        cp_async16(stg + 17408 + (row * 136 + c8) * 2, Kgl + (size_t)row * HDIM + c8);
        int vrow = idx >> 3, vc8 = (idx & 7) * 8;
        cp_async16(stg + 34816 + (vrow * 72 + vc8) * 2, Vgh + (size_t)vrow * TOTLEN + vc8);
        cp_async16(stg + 53248 + (vrow * 72 + vc8) * 2, Vgl + (size_t)vrow * TOTLEN + vc8);
    }
}

__global__ __launch_bounds__(256)
void attn_mma_kernel(float* __restrict__ out_na)
{
    extern __shared__ char sm[];
    float* Ss = (float*)(sm + 178176);
    __nv_bfloat16* Phb = (__nv_bfloat16*)(sm + 195584);
    __nv_bfloat16* Plb = (__nv_bfloat16*)(sm + 204800);
    float* rm = (float*)(sm + 214016);
    float* rl = rm + 64;
    float* rc = rm + 128;

    const uint32_t sb  = smem_u32(sm);
    const uint32_t sQh = sb, sQl = sb + 17408;
    const uint32_t sPh = sb + 195584, sPl = sb + 204800;

    const int qt = blockIdx.x;
    const int bh = blockIdx.y;
    const int q0 = qt * 64;
    const int t = threadIdx.x, lane = t & 31, wid = t >> 5;
    const int wm = wid >> 2, wn = wid & 3;
    const int m_base = wm * 32;

    const int n_kv = 17 + qt;

    attn_prefetch(sb + ATT_KV0, bh, 0, t);
    CP_COMMIT();
    {
        const __nv_bfloat16* Qgh = g_qh + ((size_t)bh * SEQ + q0) * HDIM;
        const __nv_bfloat16* Qgl = g_ql + ((size_t)bh * SEQ + q0) * HDIM;
#pragma unroll
        for (int l = 0; l < 4; l++) {
            int idx = t + l * 256;
            int row = idx >> 4, c8 = (idx & 15) * 8;
            *(uint4*)(sm + (row * 136 + c8) * 2) = *(const uint4*)(Qgh + (size_t)row * HDIM + c8);
            *(uint4*)(sm + 17408 + (row * 136 + c8) * 2) = *(const uint4*)(Qgl + (size_t)row * HDIM + c8);
        }
    }
    if (t < 64) { rm[t] = -1e30f; rl[t] = 0.f; }

    float oacc[2][4][4];
#pragma unroll
    for (int i = 0; i < 2; i++)
#pragma unroll
        for (int j = 0; j < 4; j++)
#pragma unroll
            for (int l = 0; l < 4; l++) oacc[i][j][l] = 0.f;

    const int lrA = lane & 15, lcA = ((lane >> 4) & 1) << 3;
    const int gB = lane >> 3;
    const int lrB = (lane & 7) + ((gB >> 1) << 3), lcB = (gB & 1) << 3;

    for (int kt = 0; kt < n_kv; kt++) {
        const int kv0 = kt * 64;
        if (kt + 1 < n_kv) {
            attn_prefetch(sb + ATT_KV0 + ((kt + 1) & 1) * ATT_KVST, bh, kv0 + 64, t);
            CP_COMMIT();
            CP_WAIT(1);
        } else {
            CP_WAIT(0);
        }
        __syncthreads();

        const uint32_t sKV = sb + ATT_KV0 + (kt & 1) * ATT_KVST;
        const uint32_t sKh = sKV, sKl = sKV + 17408;
        const uint32_t sVh = sKV + 34816, sVl = sKV + 53248;

        float sa[2][2][4];
#pragma unroll
        for (int i = 0; i < 2; i++)
#pragma unroll
            for (int j = 0; j < 2; j++)
#pragma unroll
                for (int l = 0; l < 4; l++) sa[i][j][l] = 0.f;

#pragma unroll
        for (int ks = 0; ks < 8; ks++) {
            const int k0b = ks * 32;
            uint32_t qf0[4], qf1[4], kh[4], kl[4];
            LDSM4(qf0[0], qf0[1], qf0[2], qf0[3],
                  sQh + ((m_base + lrA) * 136 + lcA) * 2 + k0b);
            LDSM4(qf1[0], qf1[1], qf1[2], qf1[3],
                  sQh + ((m_base + 16 + lrA) * 136 + lcA) * 2 + k0b);
            LDSM4(kh[0], kh[1], kh[2], kh[3],
                  sKh + ((wn * 16 + lrB) * 136 + lcB) * 2 + k0b);
            mma_bf16(sa[0][0], qf0, &kh[0]); mma_bf16(sa[0][1], qf0, &kh[2]);
            mma_bf16(sa[1][0], qf1, &kh[0]); mma_bf16(sa[1][1], qf1, &kh[2]);
            LDSM4(kl[0], kl[1], kl[2], kl[3],
                  sKl + ((wn * 16 + lrB) * 136 + lcB) * 2 + k0b);
            mma_bf16(sa[0][0], qf0, &kl[0]); mma_bf16(sa[0][1], qf0, &kl[2]);
            mma_bf16(sa[1][0], qf1, &kl[0]); mma_bf16(sa[1][1], qf1, &kl[2]);
            LDSM4(qf0[0], qf0[1], qf0[2], qf0[3],
                  sQl + ((m_base + lrA) * 136 + lcA) * 2 + k0b);
            LDSM4(qf1[0], qf1[1], qf1[2], qf1[3],
                  sQl + ((m_base + 16 + lrA) * 136 + lcA) * 2 + k0b);
            mma_bf16(sa[0][0], qf0, &kh[0]); mma_bf16(sa[0][1], qf0, &kh[2]);
            mma_bf16(sa[1][0], qf1, &kh[0]); mma_bf16(sa[1][1], qf1, &kh[2]);
        }
        {
            const float scale = 0.088388347648318447f;
#pragma unroll
            for (int mt = 0; mt < 2; mt++) {
                int r0 = m_base + mt * 16 + (lane >> 2);
                int lim0 = CACHEDLEN + q0 + r0;
#pragma unroll
                for (int nt = 0; nt < 2; nt++) {
                    int c = wn * 16 + nt * 8 + (lane & 3) * 2;
                    int jg = kv0 + c;
                    Ss[r0 * 68 + c]           = (jg     <= lim0)     ? sa[mt][nt][0] * scale : -1e30f;
                    Ss[r0 * 68 + c + 1]       = (jg + 1 <= lim0)     ? sa[mt][nt][1] * scale : -1e30f;
                    Ss[(r0 + 8) * 68 + c]     = (jg     <= lim0 + 8) ? sa[mt][nt][2] * scale : -1e30f;
                    Ss[(r0 + 8) * 68 + c + 1] = (jg + 1 <= lim0 + 8) ? sa[mt][nt][3] * scale : -1e30f;
                }
            }
        }
        __syncthreads();

        {
            int row = t >> 2, seg = t & 3;
            float vals[16];
            float mx = -1e30f;
#pragma unroll
            for (int j = 0; j < 16; j++) {
                vals[j] = Ss[row * 68 + seg + 4 * j];
                mx = fmaxf(mx, vals[j]);
            }
            mx = fmaxf(mx, __shfl_xor_sync(0xFFFFFFFFu, mx, 1));
            mx = fmaxf(mx, __shfl_xor_sync(0xFFFFFFFFu, mx, 2));
            float mo = rm[row];
            float mxn = fmaxf(mo, mx);
            float sum = 0.f;
#pragma unroll
            for (int j = 0; j < 16; j++) {
                float p = __expf(vals[j] - mxn);
                sum += p;
                __nv_bfloat16 ph = __float2bfloat16(p);
                Phb[row * 72 + seg + 4 * j] = ph;
                Plb[row * 72 + seg + 4 * j] = __float2bfloat16(p - __bfloat162float(ph));
            }
            sum += __shfl_xor_sync(0xFFFFFFFFu, sum, 1);
            sum += __shfl_xor_sync(0xFFFFFFFFu, sum, 2);
            if (seg == 0) {
                float corr = __expf(mo - mxn);
                rl[row] = rl[row] * corr + sum;
                rm[row] = mxn;
                rc[row] = corr;
            }
        }
        __syncthreads();

#pragma unroll
        for (int mt = 0; mt < 2; mt++) {
            float c0 = rc[m_base + mt * 16 + (lane >> 2)];
            float c1 = rc[m_base + mt * 16 + 8 + (lane >> 2)];
#pragma unroll
            for (int nt = 0; nt < 4; nt++) {
                oacc[mt][nt][0] *= c0; oacc[mt][nt][1] *= c0;
                oacc[mt][nt][2] *= c1; oacc[mt][nt][3] *= c1;
            }
        }
#pragma unroll
        for (int ks = 0; ks < 4; ks++) {
            const int k0b = ks * 32;
            uint32_t pf0[4], pf1[4], vh0[4], vh1[4], vx0[4], vx1[4];
            LDSM4(pf0[0], pf0[1], pf0[2], pf0[3],
                  sPh + ((m_base + lrA) * 72 + lcA) * 2 + k0b);
            LDSM4(pf1[0], pf1[1], pf1[2], pf1[3],
                  sPh + ((m_base + 16 + lrA) * 72 + lcA) * 2 + k0b);
            LDSM4(vh0[0], vh0[1], vh0[2], vh0[3],
                  sVh + ((wn * 32 + lrB) * 72 + lcB) * 2 + k0b);
            LDSM4(vh1[0], vh1[1], vh1[2], vh1[3],
                  sVh + ((wn * 32 + 16 + lrB) * 72 + lcB) * 2 + k0b);
            mma_bf16(oacc[0][0], pf0, &vh0[0]); mma_bf16(oacc[0][1], pf0, &vh0[2]);
            mma_bf16(oacc[0][2], pf0, &vh1[0]); mma_bf16(oacc[0][3], pf0, &vh1[2]);
            mma_bf16(oacc[1][0], pf1, &vh0[0]); mma_bf16(oacc[1][1], pf1, &vh0[2]);
            mma_bf16(oacc[1][2], pf1, &vh1[0]); mma_bf16(oacc[1][3], pf1, &vh1[2]);
            LDSM4(vx0[0], vx0[1], vx0[2], vx0[3],
                  sVl + ((wn * 32 + lrB) * 72 + lcB) * 2 + k0b);
            LDSM4(vx1[0], vx1[1], vx1[2], vx1[3],
                  sVl + ((wn * 32 + 16 + lrB) * 72 + lcB) * 2 + k0b);
            mma_bf16(oacc[0][0], pf0, &vx0[0]); mma_bf16(oacc[0][1], pf0, &vx0[2]);
            mma_bf16(oacc[0][2], pf0, &vx1[0]); mma_bf16(oacc[0][3], pf0, &vx1[2]);
            mma_bf16(oacc[1][0], pf1, &vx0[0]); mma_bf16(oacc[1][1], pf1, &vx0[2]);
            mma_bf16(oacc[1][2], pf1, &vx1[0]); mma_bf16(oacc[1][3], pf1, &vx1[2]);
            LDSM4(pf0[0], pf0[1], pf0[2], pf0[3],
                  sPl + ((m_base + lrA) * 72 + lcA) * 2 + k0b);
            LDSM4(pf1[0], pf1[1], pf1[2], pf1[3],
                  sPl + ((m_base + 16 + lrA) * 72 + lcA) * 2 + k0b);
            mma_bf16(oacc[0][0], pf0, &vh0[0]); mma_bf16(oacc[0][1], pf0, &vh0[2]);
            mma_bf16(oacc[0][2], pf0, &vh1[0]); mma_bf16(oacc[0][3], pf0, &vh1[2]);
            mma_bf16(oacc[1][0], pf1, &vh0[0]); mma_bf16(oacc[1][1], pf1, &vh0[2]);
            mma_bf16(oacc[1][2], pf1, &vh1[0]); mma_bf16(oacc[1][3], pf1, &vh1[2]);
        }
        __syncthreads();
    }

    const int b = bh >> 4, h = bh & 15;
#pragma unroll
    for (int mt = 0; mt < 2; mt++) {
        int r0 = m_base + mt * 16 + (lane >> 2);
        int r1 = r0 + 8;
        float i0 = 1.f / rl[r0], i1 = 1.f / rl[r1];
#pragma unroll
        for (int nt = 0; nt < 4; nt++) {
            int c = wn * 32 + nt * 8 + (lane & 3) * 2;
            float o00 = oacc[mt][nt][0] * i0, o01 = oacc[mt][nt][1] * i0;
            float o10 = oacc[mt][nt][2] * i1, o11 = oacc[mt][nt][3] * i1;
            float2 v0 = { o00, o01 }, v1 = { o10, o11 };
            *(float2*)(out_na + ((size_t)bh * TOTLEN + CACHEDLEN + q0 + r0) * HDIM + c) = v0;
            *(float2*)(out_na + ((size_t)bh * TOTLEN + CACHEDLEN + q0 + r1) * HDIM + c) = v1;
            size_t x0 = ((size_t)(b * SEQ + q0 + r0)) * HIDDEN + h * HDIM + c;
            size_t x1 = ((size_t)(b * SEQ + q0 + r1)) * HIDDEN + h * HDIM + c;
            __nv_bfloat162 ph, pl;
            split2(o00, ph.x, pl.x); split2(o01, ph.y, pl.y);
            *(__nv_bfloat162*)(g_xh + x0) = ph;
            *(__nv_bfloat162*)(g_xl + x0) = pl;
            split2(o10, ph.x, pl.x); split2(o11, ph.y, pl.y);
            *(__nv_bfloat162*)(g_xh + x1) = ph;
            *(__nv_bfloat162*)(g_xl + x1) = pl;
        }
    }
}

// ---------------- launch ------------------------------------------------------
extern "C" void kernel_launch(void* const* d_in, const int* in_sizes, int n_in,
                              void* d_out, int out_size)
{
    const float* hidden   = (const float*)d_in[0];
    const float* cached_k = (const float*)d_in[2];
    const float* cached_a = (const float*)d_in[3];
    const float* W_qkv    = (const float*)d_in[4];
    const float* b_qkv    = (const float*)d_in[5];
    const float* W_dense  = (const float*)d_in[6];
    const float* b_dense  = (const float*)d_in[7];

    float* out      = (float*)d_out;
    float* out_main = out;
    float* out_fk   = out + (size_t)BATCH * SEQ * HIDDEN;
    float* out_na   = out_fk + (size_t)BATCH * NHEADS * TOTLEN * HDIM;

    static __nv_bfloat16 *ah_p, *al_p, *wqh_p, *wql_p, *wdh_p, *wdl_p, *xh_p, *xl_p;
    static bool init = false;
    if (!init) {
        cudaGetSymbolAddress((void**)&ah_p,  g_ah);
        cudaGetSymbolAddress((void**)&al_p,  g_al);
        cudaGetSymbolAddress((void**)&wqh_p, g_wqh);
        cudaGetSymbolAddress((void**)&wql_p, g_wql);
        cudaGetSymbolAddress((void**)&wdh_p, g_wdh);
        cudaGetSymbolAddress((void**)&wdl_p, g_wdl);
        cudaGetSymbolAddress((void**)&xh_p,  g_xh);
        cudaGetSymbolAddress((void**)&xl_p,  g_xl);
        cudaFuncSetAttribute(gemm_mma_split_kernel,
                             cudaFuncAttributeMaxDynamicSharedMemorySize, G_SMEM);
        cudaFuncSetAttribute(qkv_fused_kernel,
                             cudaFuncAttributeMaxDynamicSharedMemorySize, G_SMEM);
        cudaFuncSetAttribute(attn_mma_kernel,
                             cudaFuncAttributeMaxDynamicSharedMemorySize, ATT_SMEM);
        init = true;
    }

    // 1. conv_split(hidden) || transpose+split W_qkv || rope tables
    pre_kernel<<<PRE_CTAS + 1, 256>>>(
        (const float4*)hidden, (__nv_bfloat162*)ah_p, (__nv_bfloat162*)al_p, W_qkv);

    // 2. QKV GEMM (fused rope/split/V^T epilogue) + side work
    qkv_fused_kernel<<<QKV_GEMM_CTAS + NSIDE, 256, G_SMEM>>>(
        ah_p, al_p, wqh_p, wql_p, b_qkv,
        cached_k, cached_a, out_fk, out_na, W_dense);

    // 3. tensor-core attention (cp.async double-buffered KV)
    attn_mma_kernel<<<dim3(SEQ / 64, BATCH * NHEADS), 256, ATT_SMEM>>>(out_na);

    // 4. dense projection
    gemm_mma_split_kernel<<<dim3(HIDDEN / 128, MTOK / 128), 256, G_SMEM>>>(
        xh_p, xl_p, wdh_p, wdl_p, b_dense, out_main, MTOK, HIDDEN, HIDDEN);
}

// round 13
// speedup vs baseline: 1.0676x; 1.0656x over previous
#include <cuda_runtime.h>
#include <cuda_bf16.h>
#include <math.h>
#include <stdint.h>

#define HIDDEN 2048
#define NHEADS 16
#define HDIM 128
#define RDIM 32
#define BATCH 2
#define SEQ 1024
#define CACHEDLEN 1024
#define TOTLEN 2048
#define MTOK (BATCH*SEQ)

// ============================ scratch globals ================================
__device__ float g_qkv[(size_t)MTOK * 3 * HIDDEN];
__device__ float g_v[(size_t)BATCH * NHEADS * SEQ * HDIM];      // fp32 V staging
__device__ __nv_bfloat16 g_qh[(size_t)BATCH * NHEADS * SEQ * HDIM];
__device__ __nv_bfloat16 g_ql[(size_t)BATCH * NHEADS * SEQ * HDIM];
__device__ __nv_bfloat16 g_kh[(size_t)BATCH * NHEADS * TOTLEN * HDIM];
__device__ __nv_bfloat16 g_kl[(size_t)BATCH * NHEADS * TOTLEN * HDIM];
__device__ __nv_bfloat16 g_vth[(size_t)BATCH * NHEADS * HDIM * TOTLEN];  // [bh][d][t]
__device__ __nv_bfloat16 g_vtl[(size_t)BATCH * NHEADS * HDIM * TOTLEN];
__device__ __nv_bfloat16 g_ah[(size_t)MTOK * HIDDEN];
__device__ __nv_bfloat16 g_al[(size_t)MTOK * HIDDEN];
__device__ __nv_bfloat16 g_wqh[(size_t)3 * HIDDEN * HIDDEN];
__device__ __nv_bfloat16 g_wql[(size_t)3 * HIDDEN * HIDDEN];
__device__ __nv_bfloat16 g_wdh[(size_t)HIDDEN * HIDDEN];
__device__ __nv_bfloat16 g_wdl[(size_t)HIDDEN * HIDDEN];
__device__ __nv_bfloat16 g_xh[(size_t)MTOK * HIDDEN];
__device__ __nv_bfloat16 g_xl[(size_t)MTOK * HIDDEN];

// ============================ PTX helpers ====================================
__device__ __forceinline__ uint32_t smem_u32(const void* p) {
    uint32_t a;
    asm("{ .reg .u64 t; cvta.to.shared.u64 t, %1; cvt.u32.u64 %0, t; }" : "=r"(a) : "l"(p));
    return a;
}
#define LDSM4(r0, r1, r2, r3, a) \
    asm volatile("ldmatrix.sync.aligned.m8n8.x4.shared.b16 {%0,%1,%2,%3}, [%4];" \
        : "=r"(r0), "=r"(r1), "=r"(r2), "=r"(r3) : "r"(a))
__device__ __forceinline__ void mma_bf16(float* c, const uint32_t* a, const uint32_t* b) {
    asm volatile("mma.sync.aligned.m16n8k16.row.col.f32.bf16.bf16.f32 "
        "{%0,%1,%2,%3}, {%4,%5,%6,%7}, {%8,%9}, {%0,%1,%2,%3};"
        : "+f"(c[0]), "+f"(c[1]), "+f"(c[2]), "+f"(c[3])
        : "r"(a[0]), "r"(a[1]), "r"(a[2]), "r"(a[3]), "r"(b[0]), "r"(b[1]));
}
__device__ __forceinline__ void cp_async16(uint32_t dst, const void* src) {
    asm volatile("cp.async.cg.shared.global [%0], [%1], 16;" :: "r"(dst), "l"(src));
}
#define CP_COMMIT() asm volatile("cp.async.commit_group;" ::: "memory")
#define CP_WAIT(n)  asm volatile("cp.async.wait_group %0;" :: "n"(n) : "memory")

__device__ __forceinline__ void split2(float v, __nv_bfloat16& h, __nv_bfloat16& l) {
    h = __float2bfloat16(v);
    l = __float2bfloat16(v - __bfloat162float(h));
}

// ====== split-bf16 GEMM body (cp.async double-buffered) ======================
#define BK 32
#define ASTRIDE 40
#define TILE_BYTES (128 * ASTRIDE * 2)    // 10240
#define STAGE_BYTES (4 * TILE_BYTES)      // 40960
#define G_SMEM (2 * STAGE_BYTES)          // 81920  -> 2 CTAs/SM

__device__ __forceinline__
void gemm_body(int bx, int by,
               const __nv_bfloat16* __restrict__ Ah,
               const __nv_bfloat16* __restrict__ Al,
               const __nv_bfloat16* __restrict__ Bh,
               const __nv_bfloat16* __restrict__ Bl,
               const float* __restrict__ bias,
               float* __restrict__ C, int M, int N, int K, char* sm)
{
    const uint32_t sb = smem_u32(sm);
    const int t    = threadIdx.x;
    const int lane = t & 31, wid = t >> 5;
    const int wm = wid >> 2, wn = wid & 3;
    const int m_base = wm * 64, n_base = wn * 32;
    const int m0 = by * 128, n0 = bx * 128;

    const int lrowA = lane & 15;
    const int lcolA = ((lane >> 4) & 1) << 3;
    const int gB    = lane >> 3;
    const int lrowB = (lane & 7) + ((gB >> 1) << 3);
    const int lcolB = (gB & 1) << 3;

    const uint32_t oAh = 0 * TILE_BYTES + ((m_base + lrowA) * ASTRIDE + lcolA) * 2;
    const uint32_t oAl = 1 * TILE_BYTES + ((m_base + lrowA) * ASTRIDE + lcolA) * 2;
    const uint32_t oBh = 2 * TILE_BYTES + ((n_base + lrowB) * ASTRIDE + lcolB) * 2;
    const uint32_t oBl = 3 * TILE_BYTES + ((n_base + lrowB) * ASTRIDE + lcolB) * 2;

    const int ldrow = t >> 2;
    const int ldc   = (t & 3) * 8;
    const uint32_t ldst = (ldrow * ASTRIDE + ldc) * 2;

    const __nv_bfloat16* gsrc[4] = {
        Ah + (size_t)m0 * K, Al + (size_t)m0 * K,
        Bh + (size_t)n0 * K, Bl + (size_t)n0 * K };

    float acc[4][4][4];
#pragma unroll
    for (int i = 0; i < 4; i++)
#pragma unroll
        for (int j = 0; j < 4; j++)
#pragma unroll
            for (int l = 0; l < 4; l++) acc[i][j][l] = 0.f;

    const int NK = K / BK;

    {
        uint32_t db = sb;
#pragma unroll
        for (int tile = 0; tile < 4; tile++) {
            const __nv_bfloat16* s = gsrc[tile] + ldc;
#pragma unroll
            for (int l = 0; l < 2; l++)
                cp_async16(db + tile * TILE_BYTES + ldst + l * 64 * ASTRIDE * 2,
                           s + (size_t)(ldrow + l * 64) * K);
        }
        CP_COMMIT();
    }

    for (int kci = 0; kci < NK; kci++) {
        if (kci + 1 < NK) {
            const int kc = (kci + 1) * BK;
            uint32_t db = sb + ((kci + 1) & 1) * STAGE_BYTES;
#pragma unroll
            for (int tile = 0; tile < 4; tile++) {
                const __nv_bfloat16* s = gsrc[tile] + kc + ldc;
#pragma unroll
                for (int l = 0; l < 2; l++)
                    cp_async16(db + tile * TILE_BYTES + ldst + l * 64 * ASTRIDE * 2,
                               s + (size_t)(ldrow + l * 64) * K);
            }
            CP_COMMIT();
            CP_WAIT(1);
        } else {
            CP_WAIT(0);
        }
        __syncthreads();

        const uint32_t stg = sb + (kci & 1) * STAGE_BYTES;
        const uint32_t aAh0 = stg + oAh, aAl0 = stg + oAl;
        const uint32_t aBh0 = stg + oBh, aBl0 = stg + oBl;

#pragma unroll
        for (int ks = 0; ks < BK / 16; ks++) {
            const int k0b = (ks * 16) * 2;
            uint32_t ah[4][4], bh[2][4];
#pragma unroll
            for (int mt = 0; mt < 4; mt++)
                LDSM4(ah[mt][0], ah[mt][1], ah[mt][2], ah[mt][3],
                      aAh0 + mt * 16 * ASTRIDE * 2 + k0b);
#pragma unroll
            for (int nt = 0; nt < 2; nt++)
                LDSM4(bh[nt][0], bh[nt][1], bh[nt][2], bh[nt][3],
                      aBh0 + nt * 16 * ASTRIDE * 2 + k0b);
#pragma unroll
            for (int mt = 0; mt < 4; mt++)
#pragma unroll
                for (int nt = 0; nt < 2; nt++) {
                    mma_bf16(acc[mt][nt * 2 + 0], ah[mt], &bh[nt][0]);
                    mma_bf16(acc[mt][nt * 2 + 1], ah[mt], &bh[nt][2]);
                }
            uint32_t bl[2][4];
#pragma unroll
            for (int nt = 0; nt < 2; nt++)
                LDSM4(bl[nt][0], bl[nt][1], bl[nt][2], bl[nt][3],
                      aBl0 + nt * 16 * ASTRIDE * 2 + k0b);
#pragma unroll
            for (int mt = 0; mt < 4; mt++)
#pragma unroll
                for (int nt = 0; nt < 2; nt++) {
                    mma_bf16(acc[mt][nt * 2 + 0], ah[mt], &bl[nt][0]);
                    mma_bf16(acc[mt][nt * 2 + 1], ah[mt], &bl[nt][2]);
                }
#pragma unroll
            for (int mt = 0; mt < 4; mt++)
                LDSM4(ah[mt][0], ah[mt][1], ah[mt][2], ah[mt][3],
                      aAl0 + mt * 16 * ASTRIDE * 2 + k0b);
#pragma unroll
            for (int mt = 0; mt < 4; mt++)
#pragma unroll
                for (int nt = 0; nt < 2; nt++) {
                    mma_bf16(acc[mt][nt * 2 + 0], ah[mt], &bh[nt][0]);
                    mma_bf16(acc[mt][nt * 2 + 1], ah[mt], &bh[nt][2]);
                }
        }
        __syncthreads();
    }

    const int row0 = m0 + m_base + (lane >> 2);
    const int col0 = n0 + n_base + (lane & 3) * 2;
#pragma unroll
    for (int mt = 0; mt < 4; mt++) {
#pragma unroll
        for (int n = 0; n < 4; n++) {
            int r = row0 + mt * 16;
            int c = col0 + n * 8;
            float b0 = bias[c], b1 = bias[c + 1];
            float2 v0 = { acc[mt][n][0] + b0, acc[mt][n][1] + b1 };
            float2 v1 = { acc[mt][n][2] + b0, acc[mt][n][3] + b1 };
            *(float2*)(C + (size_t)r * N + c) = v0;
            *(float2*)(C + (size_t)(r + 8) * N + c) = v1;
        }
    }
}

// plain GEMM kernel (dense projection)
__global__ __launch_bounds__(256, 2)
void gemm_mma_split_kernel(const __nv_bfloat16* __restrict__ Ah,
                           const __nv_bfloat16* __restrict__ Al,
                           const __nv_bfloat16* __restrict__ Bh,
                           const __nv_bfloat16* __restrict__ Bl,
                           const float* __restrict__ bias,
                           float* __restrict__ C, int M, int N, int K)
{
    extern __shared__ char sm[];
    gemm_body(blockIdx.x, blockIdx.y, Ah, Al, Bh, Bl, bias, C, M, N, K, sm);
}

// ====== fused QKV GEMM + side work (cache copies, V^T, W_dense split) ========
#define QKV_GEMM_CTAS 768    // 48 x 16
#define NSIDE 128
#define NJOB_CACHE 4096      // 32 bh x 32 t-tiles x 4 d-tiles
#define NJOB_TOT   8192      // + 4096 W_dense 32x32 tiles

__global__ __launch_bounds__(256, 2)
void qkv_fused_kernel(const __nv_bfloat16* __restrict__ Ah,
                      const __nv_bfloat16* __restrict__ Al,
                      const __nv_bfloat16* __restrict__ Bh,
                      const __nv_bfloat16* __restrict__ Bl,
                      const float* __restrict__ bias,
                      float* __restrict__ C,
                      const float* __restrict__ ck,
                      const float* __restrict__ ca,
                      float* __restrict__ out_fk,
                      float* __restrict__ out_na,
                      const float* __restrict__ Wd)
{
    extern __shared__ char sm[];
    const int gx = blockIdx.x;
    if (gx < QKV_GEMM_CTAS) {
        gemm_body(gx % 48, gx / 48, Ah, Al, Bh, Bl, bias, C,
                  MTOK, 3 * HIDDEN, HIDDEN, sm);
        return;
    }
    // ---------------- side work -------------------------------------------
    float (*s)[33] = (float(*)[33])sm;
    const int tx = threadIdx.x & 31, ty = threadIdx.x >> 5;
    for (int job = gx - QKV_GEMM_CTAS; job < NJOB_TOT; job += NSIDE) {
        if (job < NJOB_CACHE) {
            const int dt = job & 3, tt = (job >> 2) & 31, bh = job >> 7;
            const int t0 = tt * 32, d0 = dt * 32;
#pragma unroll
            for (int i = 0; i < 32; i += 8) {
                int row = t0 + ty + i;
                size_t si = ((size_t)bh * CACHEDLEN + row) * HDIM + d0 + tx;
                size_t di = ((size_t)bh * TOTLEN + row) * HDIM + d0 + tx;
                float v = ck[si];
                out_fk[di] = v;
                __nv_bfloat16 h, l; split2(v, h, l);
                g_kh[di] = h; g_kl[di] = l;
            }
#pragma unroll
            for (int i = 0; i < 32; i += 8) {
                int row = t0 + ty + i;
                size_t si = ((size_t)bh * CACHEDLEN + row) * HDIM + d0 + tx;
                float v = ca[si];
                out_na[((size_t)bh * TOTLEN + row) * HDIM + d0 + tx] = v;
                s[ty + i][tx] = v;
            }
            __syncthreads();
#pragma unroll
            for (int i = 0; i < 32; i += 8) {
                float v = s[tx][ty + i];
                size_t o = (size_t)bh * HDIM * TOTLEN
                         + (size_t)(d0 + ty + i) * TOTLEN + t0 + tx;
                __nv_bfloat16 h, l; split2(v, h, l);
                g_vth[o] = h; g_vtl[o] = l;
            }
            __syncthreads();
        } else {
            const int j2 = job - NJOB_CACHE;
            const int n0 = (j2 & 63) * 32, k0 = (j2 >> 6) * 32;
#pragma unroll
            for (int i = 0; i < 32; i += 8)
                s[ty + i][tx] = Wd[(size_t)(k0 + ty + i) * HIDDEN + n0 + tx];
            __syncthreads();
#pragma unroll
            for (int i = 0; i < 32; i += 8) {
                float v = s[tx][ty + i];
                size_t o = (size_t)(n0 + ty + i) * HIDDEN + k0 + tx;
                __nv_bfloat16 h, l; split2(v, h, l);
                g_wdh[o] = h; g_wdl[o] = l;
            }
            __syncthreads();
        }
    }
}

// ====== pre kernel: conv_split(hidden) || transpose+split W_qkv ==============
#define PRE_SPLIT_CTAS 1024
#define PRE_CTAS 2048
#define NJOB_WQ 12288        // 192 n-tiles x 64 k-tiles

__global__ void pre_kernel(const float4* __restrict__ hidden,
                           __nv_bfloat162* __restrict__ oh,
                           __nv_bfloat162* __restrict__ ol,
                           const float* __restrict__ Wq)
{
    __shared__ float s[32][33];
    if (blockIdx.x < PRE_SPLIT_CTAS) {
        int base = blockIdx.x * 256 + threadIdx.x;
#pragma unroll
        for (int l = 0; l < 4; l++) {
            int i = base + l * (PRE_SPLIT_CTAS * 256);
            float4 v = hidden[i];
            __nv_bfloat162 p, q;
            split2(v.x, p.x, q.x); split2(v.y, p.y, q.y);
            oh[i * 2 + 0] = p; ol[i * 2 + 0] = q;
            split2(v.z, p.x, q.x); split2(v.w, p.y, q.y);
            oh[i * 2 + 1] = p; ol[i * 2 + 1] = q;
        }
        return;
    }
    const int tx = threadIdx.x & 31, ty = threadIdx.x >> 5;
    for (int job = blockIdx.x - PRE_SPLIT_CTAS; job < NJOB_WQ;
         job += PRE_CTAS - PRE_SPLIT_CTAS) {
        const int n0 = (job % 192) * 32, k0 = (job / 192) * 32;
#pragma unroll
        for (int i = 0; i < 32; i += 8)
            s[ty + i][tx] = Wq[(size_t)(k0 + ty + i) * (3 * HIDDEN) + n0 + tx];
        __syncthreads();
#pragma unroll
        for (int i = 0; i < 32; i += 8) {
            float v = s[tx][ty + i];
            size_t o = (size_t)(n0 + ty + i) * HIDDEN + k0 + tx;
            __nv_bfloat16 h, l; split2(v, h, l);
            g_wqh[o] = h; g_wql[o] = l;
        }
        __syncthreads();
    }
}

// ---------------- RoPE: qkv -> bf16 hi/lo Q,K + fp32 V + full_key ------------
__global__ void rope_kernel(float* __restrict__ out_fullkey)
{
    int n = blockIdx.x * blockDim.x + threadIdx.x;
    int d = n & (HDIM - 1);
    int s = (n >> 7) & (SEQ - 1);
    int h = (n >> 17) & (NHEADS - 1);
    int b = n >> 21;
    int bh = b * NHEADS + h;

    const float* base = g_qkv + (size_t)(b * SEQ + s) * (3 * HIDDEN) + h * HDIM;
    float q = base[d];
    float k = base[HIDDEN + d];
    float v = base[2 * HIDDEN + d];

    if (d < RDIM) {
        int   dp   = (d < RDIM / 2) ? d + RDIM / 2 : d - RDIM / 2;
        float sign = (d < RDIM / 2) ? -1.f : 1.f;
        float qp = base[dp];
        float kp = base[HIDDEN + dp];
        double pos = (double)(CACHEDLEN + s);
        double jj  = (double)(d & (RDIM / 2 - 1));
        double inv = exp(-jj * (1.0 / 16.0) * 9.210340371976184);
        double ang = pos * inv;
        float c  = (float)cos(ang);
        float sn = (float)sin(ang);
        q = q * c + sign * qp * sn;
        k = k * c + sign * kp * sn;
    }
    size_t qo = ((size_t)bh * SEQ + s) * HDIM + d;
    __nv_bfloat16 qh, ql; split2(q, qh, ql);
    g_qh[qo] = qh; g_ql[qo] = ql;
    g_v[qo] = v;
    size_t ko = ((size_t)bh * TOTLEN + CACHEDLEN + s) * HDIM + d;
    __nv_bfloat16 kh, kl; split2(k, kh, kl);
    g_kh[ko] = kh; g_kl[ko] = kl;
    out_fullkey[ko] = k;
}

// ---------------- V transpose (new half only) --------------------------------
__global__ void vtrans_new_kernel()
{
    __shared__ float s[32][33];
    int t0 = CACHEDLEN + blockIdx.x * 32;
    int d0 = blockIdx.y * 32;
    int bh = blockIdx.z;
    int tx = threadIdx.x, ty = threadIdx.y;
    const float* src = g_v + ((size_t)bh * SEQ + (t0 - CACHEDLEN)) * HDIM;
#pragma unroll
    for (int i = 0; i < 32; i += 8)
        s[ty + i][tx] = src[(size_t)(ty + i) * HDIM + d0 + tx];
    __syncthreads();
#pragma unroll
    for (int i = 0; i < 32; i += 8) {
        float v = s[tx][ty + i];
        size_t o = (size_t)bh * HDIM * TOTLEN + (size_t)(d0 + ty + i) * TOTLEN + t0 + tx;
        __nv_bfloat16 h, l; split2(v, h, l);
        g_vth[o] = h; g_vtl[o] = l;
    }
}

// ==== tensor-core flash attention (split-bf16, cp.async double-buffered) =====
#define ATT_KV0   34816
#define ATT_KVST  71680
#define ATT_SMEM  214784

__device__ __forceinline__
void attn_prefetch(uint32_t stg, int bh, int kv0, int t)
{
    const __nv_bfloat16* Kgh = g_kh + ((size_t)bh * TOTLEN + kv0) * HDIM;
    const __nv_bfloat16* Kgl = g_kl + ((size_t)bh * TOTLEN + kv0) * HDIM;
    const __nv_bfloat16* Vgh = g_vth + (size_t)bh * HDIM * TOTLEN + kv0;
    const __nv_bfloat16* Vgl = g_vtl + (size_t)bh * HDIM * TOTLEN + kv0;
#pragma unroll
    for (int l = 0; l < 4; l++) {
        int idx = t + l * 256;
        int row = idx >> 4, c8 = (idx & 15) * 8;
        cp_async16(stg + (row * 136 + c8) * 2, Kgh + (size_t)row * HDIM + c8);
        cp_async16(stg + 17408 + (row * 136 + c8) * 2, Kgl + (size_t)row * HDIM + c8);
        int vrow = idx >> 3, vc8 = (idx & 7) * 8;
        cp_async16(stg + 34816 + (vrow * 72 + vc8) * 2, Vgh + (size_t)vrow * TOTLEN + vc8);
        cp_async16(stg + 53248 + (vrow * 72 + vc8) * 2, Vgl + (size_t)vrow * TOTLEN + vc8);
    }
}

__global__ __launch_bounds__(256)
void attn_mma_kernel(float* __restrict__ out_na)
{
    extern __shared__ char sm[];
    float* Ss = (float*)(sm + 178176);
    __nv_bfloat16* Phb = (__nv_bfloat16*)(sm + 195584);
    __nv_bfloat16* Plb = (__nv_bfloat16*)(sm + 204800);
    float* rm = (float*)(sm + 214016);
    float* rl = rm + 64;
    float* rc = rm + 128;

    const uint32_t sb  = smem_u32(sm);
    const uint32_t sQh = sb, sQl = sb + 17408;
    const uint32_t sPh = sb + 195584, sPl = sb + 204800;

    // LPT scheduling: longest CTAs (largest qt) launch first
    const int qt = (gridDim.x - 1) - blockIdx.x;
    const int bh = blockIdx.y;
    const int q0 = qt * 64;
    const int t = threadIdx.x, lane = t & 31, wid = t >> 5;
    const int wm = wid >> 2, wn = wid & 3;
    const int m_base = wm * 32;

    const int n_kv = 17 + qt;

    attn_prefetch(sb + ATT_KV0, bh, 0, t);
    CP_COMMIT();
    {
        const __nv_bfloat16* Qgh = g_qh + ((size_t)bh * SEQ + q0) * HDIM;
        const __nv_bfloat16* Qgl = g_ql + ((size_t)bh * SEQ + q0) * HDIM;
#pragma unroll
        for (int l = 0; l < 4; l++) {
            int idx = t + l * 256;
            int row = idx >> 4, c8 = (idx & 15) * 8;
            *(uint4*)(sm + (row * 136 + c8) * 2) = *(const uint4*)(Qgh + (size_t)row * HDIM + c8);
            *(uint4*)(sm + 17408 + (row * 136 + c8) * 2) = *(const uint4*)(Qgl + (size_t)row * HDIM + c8);
        }
    }
    if (t < 64) { rm[t] = -1e30f; rl[t] = 0.f; }

    float oacc[2][4][4];
#pragma unroll
    for (int i = 0; i < 2; i++)
#pragma unroll
        for (int j = 0; j < 4; j++)
#pragma unroll
            for (int l = 0; l < 4; l++) oacc[i][j][l] = 0.f;

    const int lrA = lane & 15, lcA = ((lane >> 4) & 1) << 3;
    const int gB = lane >> 3;
    const int lrB = (lane & 7) + ((gB >> 1) << 3), lcB = (gB & 1) << 3;

    for (int kt = 0; kt < n_kv; kt++) {
        const int kv0 = kt * 64;
        if (kt + 1 < n_kv) {
            attn_prefetch(sb + ATT_KV0 + ((kt + 1) & 1) * ATT_KVST, bh, kv0 + 64, t);
            CP_COMMIT();
            CP_WAIT(1);
        } else {
            CP_WAIT(0);
        }
        __syncthreads();

        const uint32_t sKV = sb + ATT_KV0 + (kt & 1) * ATT_KVST;
        const uint32_t sKh = sKV, sKl = sKV + 17408;
        const uint32_t sVh = sKV + 34816, sVl = sKV + 53248;

        float sa[2][2][4];
#pragma unroll
        for (int i = 0; i < 2; i++)
#pragma unroll
            for (int j = 0; j < 2; j++)
#pragma unroll
                for (int l = 0; l < 4; l++) sa[i][j][l] = 0.f;

#pragma unroll
        for (int ks = 0; ks < 8; ks++) {
            const int k0b = ks * 32;
            uint32_t qf0[4], qf1[4], kh[4], kl[4];
            LDSM4(qf0[0], qf0[1], qf0[2], qf0[3],
                  sQh + ((m_base + lrA) * 136 + lcA) * 2 + k0b);
            LDSM4(qf1[0], qf1[1], qf1[2], qf1[3],
                  sQh + ((m_base + 16 + lrA) * 136 + lcA) * 2 + k0b);
            LDSM4(kh[0], kh[1], kh[2], kh[3],
                  sKh + ((wn * 16 + lrB) * 136 + lcB) * 2 + k0b);
            mma_bf16(sa[0][0], qf0, &kh[0]); mma_bf16(sa[0][1], qf0, &kh[2]);
            mma_bf16(sa[1][0], qf1, &kh[0]); mma_bf16(sa[1][1], qf1, &kh[2]);
            LDSM4(kl[0], kl[1], kl[2], kl[3],
                  sKl + ((wn * 16 + lrB) * 136 + lcB) * 2 + k0b);
            mma_bf16(sa[0][0], qf0, &kl[0]); mma_bf16(sa[0][1], qf0, &kl[2]);
            mma_bf16(sa[1][0], qf1, &kl[0]); mma_bf16(sa[1][1], qf1, &kl[2]);
            LDSM4(qf0[0], qf0[1], qf0[2], qf0[3],
                  sQl + ((m_base + lrA) * 136 + lcA) * 2 + k0b);
            LDSM4(qf1[0], qf1[1], qf1[2], qf1[3],
                  sQl + ((m_base + 16 + lrA) * 136 + lcA) * 2 + k0b);
            mma_bf16(sa[0][0], qf0, &kh[0]); mma_bf16(sa[0][1], qf0, &kh[2]);
            mma_bf16(sa[1][0], qf1, &kh[0]); mma_bf16(sa[1][1], qf1, &kh[2]);
        }
        {
            const float scale = 0.088388347648318447f;
#pragma unroll
            for (int mt = 0; mt < 2; mt++) {
                int r0 = m_base + mt * 16 + (lane >> 2);
                int lim0 = CACHEDLEN + q0 + r0;
#pragma unroll
                for (int nt = 0; nt < 2; nt++) {
                    int c = wn * 16 + nt * 8 + (lane & 3) * 2;
                    int jg = kv0 + c;
                    Ss[r0 * 68 + c]           = (jg     <= lim0)     ? sa[mt][nt][0] * scale : -1e30f;
                    Ss[r0 * 68 + c + 1]       = (jg + 1 <= lim0)     ? sa[mt][nt][1] * scale : -1e30f;
                    Ss[(r0 + 8) * 68 + c]     = (jg     <= lim0 + 8) ? sa[mt][nt][2] * scale : -1e30f;
                    Ss[(r0 + 8) * 68 + c + 1] = (jg + 1 <= lim0 + 8) ? sa[mt][nt][3] * scale : -1e30f;
                }
            }
        }
        __syncthreads();

        {
            int row = t >> 2, seg = t & 3;
            float vals[16];
            float mx = -1e30f;
#pragma unroll
            for (int j = 0; j < 16; j++) {
                vals[j] = Ss[row * 68 + seg + 4 * j];
                mx = fmaxf(mx, vals[j]);
            }
            mx = fmaxf(mx, __shfl_xor_sync(0xFFFFFFFFu, mx, 1));
            mx = fmaxf(mx, __shfl_xor_sync(0xFFFFFFFFu, mx, 2));
            float mo = rm[row];
            float mxn = fmaxf(mo, mx);
            float sum = 0.f;
#pragma unroll
            for (int j = 0; j < 16; j++) {
                float p = __expf(vals[j] - mxn);
                sum += p;
                __nv_bfloat16 ph = __float2bfloat16(p);
                Phb[row * 72 + seg + 4 * j] = ph;
                Plb[row * 72 + seg + 4 * j] = __float2bfloat16(p - __bfloat162float(ph));
            }
            sum += __shfl_xor_sync(0xFFFFFFFFu, sum, 1);
            sum += __shfl_xor_sync(0xFFFFFFFFu, sum, 2);
            if (seg == 0) {
                float corr = __expf(mo - mxn);
                rl[row] = rl[row] * corr + sum;
                rm[row] = mxn;
                rc[row] = corr;
            }
        }
        __syncthreads();

#pragma unroll
        for (int mt = 0; mt < 2; mt++) {
            float c0 = rc[m_base + mt * 16 + (lane >> 2)];
            float c1 = rc[m_base + mt * 16 + 8 + (lane >> 2)];
#pragma unroll
            for (int nt = 0; nt < 4; nt++) {
                oacc[mt][nt][0] *= c0; oacc[mt][nt][1] *= c0;
                oacc[mt][nt][2] *= c1; oacc[mt][nt][3] *= c1;
            }
        }
#pragma unroll
        for (int ks = 0; ks < 4; ks++) {
            const int k0b = ks * 32;
            uint32_t pf0[4], pf1[4], vh0[4], vh1[4], vx0[4], vx1[4];
            LDSM4(pf0[0], pf0[1], pf0[2], pf0[3],
                  sPh + ((m_base + lrA) * 72 + lcA) * 2 + k0b);
            LDSM4(pf1[0], pf1[1], pf1[2], pf1[3],
                  sPh + ((m_base + 16 + lrA) * 72 + lcA) * 2 + k0b);
            LDSM4(vh0[0], vh0[1], vh0[2], vh0[3],
                  sVh + ((wn * 32 + lrB) * 72 + lcB) * 2 + k0b);
            LDSM4(vh1[0], vh1[1], vh1[2], vh1[3],
                  sVh + ((wn * 32 + 16 + lrB) * 72 + lcB) * 2 + k0b);
            mma_bf16(oacc[0][0], pf0, &vh0[0]); mma_bf16(oacc[0][1], pf0, &vh0[2]);
            mma_bf16(oacc[0][2], pf0, &vh1[0]); mma_bf16(oacc[0][3], pf0, &vh1[2]);
            mma_bf16(oacc[1][0], pf1, &vh0[0]); mma_bf16(oacc[1][1], pf1, &vh0[2]);
            mma_bf16(oacc[1][2], pf1, &vh1[0]); mma_bf16(oacc[1][3], pf1, &vh1[2]);
            LDSM4(vx0[0], vx0[1], vx0[2], vx0[3],
                  sVl + ((wn * 32 + lrB) * 72 + lcB) * 2 + k0b);
            LDSM4(vx1[0], vx1[1], vx1[2], vx1[3],
                  sVl + ((wn * 32 + 16 + lrB) * 72 + lcB) * 2 + k0b);
            mma_bf16(oacc[0][0], pf0, &vx0[0]); mma_bf16(oacc[0][1], pf0, &vx0[2]);
            mma_bf16(oacc[0][2], pf0, &vx1[0]); mma_bf16(oacc[0][3], pf0, &vx1[2]);
            mma_bf16(oacc[1][0], pf1, &vx0[0]); mma_bf16(oacc[1][1], pf1, &vx0[2]);
            mma_bf16(oacc[1][2], pf1, &vx1[0]); mma_bf16(oacc[1][3], pf1, &vx1[2]);
            LDSM4(pf0[0], pf0[1], pf0[2], pf0[3],
                  sPl + ((m_base + lrA) * 72 + lcA) * 2 + k0b);
            LDSM4(pf1[0], pf1[1], pf1[2], pf1[3],
                  sPl + ((m_base + 16 + lrA) * 72 + lcA) * 2 + k0b);
            mma_bf16(oacc[0][0], pf0, &vh0[0]); mma_bf16(oacc[0][1], pf0, &vh0[2]);
            mma_bf16(oacc[0][2], pf0, &vh1[0]); mma_bf16(oacc[0][3], pf0, &vh1[2]);
            mma_bf16(oacc[1][0], pf1, &vh0[0]); mma_bf16(oacc[1][1], pf1, &vh0[2]);
            mma_bf16(oacc[1][2], pf1, &vh1[0]); mma_bf16(oacc[1][3], pf1, &vh1[2]);
        }
        __syncthreads();
    }

    const int b = bh >> 4, h = bh & 15;
#pragma unroll
    for (int mt = 0; mt < 2; mt++) {
        int r0 = m_base + mt * 16 + (lane >> 2);
        int r1 = r0 + 8;
        float i0 = 1.f / rl[r0], i1 = 1.f / rl[r1];
#pragma unroll
        for (int nt = 0; nt < 4; nt++) {
            int c = wn * 32 + nt * 8 + (lane & 3) * 2;
            float o00 = oacc[mt][nt][0] * i0, o01 = oacc[mt][nt][1] * i0;
            float o10 = oacc[mt][nt][2] * i1, o11 = oacc[mt][nt][3] * i1;
            float2 v0 = { o00, o01 }, v1 = { o10, o11 };
            *(float2*)(out_na + ((size_t)bh * TOTLEN + CACHEDLEN + q0 + r0) * HDIM + c) = v0;
            *(float2*)(out_na + ((size_t)bh * TOTLEN + CACHEDLEN + q0 + r1) * HDIM + c) = v1;
            size_t x0 = ((size_t)(b * SEQ + q0 + r0)) * HIDDEN + h * HDIM + c;
            size_t x1 = ((size_t)(b * SEQ + q0 + r1)) * HIDDEN + h * HDIM + c;
            __nv_bfloat162 ph, pl;
            split2(o00, ph.x, pl.x); split2(o01, ph.y, pl.y);
            *(__nv_bfloat162*)(g_xh + x0) = ph;
            *(__nv_bfloat162*)(g_xl + x0) = pl;
            split2(o10, ph.x, pl.x); split2(o11, ph.y, pl.y);
            *(__nv_bfloat162*)(g_xh + x1) = ph;
            *(__nv_bfloat162*)(g_xl + x1) = pl;
        }
    }
}

// ---------------- launch ------------------------------------------------------
extern "C" void kernel_launch(void* const* d_in, const int* in_sizes, int n_in,
                              void* d_out, int out_size)
{
    const float* hidden   = (const float*)d_in[0];
    const float* cached_k = (const float*)d_in[2];
    const float* cached_a = (const float*)d_in[3];
    const float* W_qkv    = (const float*)d_in[4];
    const float* b_qkv    = (const float*)d_in[5];
    const float* W_dense  = (const float*)d_in[6];
    const float* b_dense  = (const float*)d_in[7];

    float* out      = (float*)d_out;
    float* out_main = out;
    float* out_fk   = out + (size_t)BATCH * SEQ * HIDDEN;
    float* out_na   = out_fk + (size_t)BATCH * NHEADS * TOTLEN * HDIM;

    static float* qkv_p;
    static __nv_bfloat16 *ah_p, *al_p, *wqh_p, *wql_p, *wdh_p, *wdl_p, *xh_p, *xl_p;
    static bool init = false;
    if (!init) {
        cudaGetSymbolAddress((void**)&qkv_p, g_qkv);
        cudaGetSymbolAddress((void**)&ah_p,  g_ah);
        cudaGetSymbolAddress((void**)&al_p,  g_al);
        cudaGetSymbolAddress((void**)&wqh_p, g_wqh);
        cudaGetSymbolAddress((void**)&wql_p, g_wql);
        cudaGetSymbolAddress((void**)&wdh_p, g_wdh);
        cudaGetSymbolAddress((void**)&wdl_p, g_wdl);
        cudaGetSymbolAddress((void**)&xh_p,  g_xh);
        cudaGetSymbolAddress((void**)&xl_p,  g_xl);
        cudaFuncSetAttribute(gemm_mma_split_kernel,
                             cudaFuncAttributeMaxDynamicSharedMemorySize, G_SMEM);
        cudaFuncSetAttribute(qkv_fused_kernel,
                             cudaFuncAttributeMaxDynamicSharedMemorySize, G_SMEM);
        cudaFuncSetAttribute(attn_mma_kernel,
                             cudaFuncAttributeMaxDynamicSharedMemorySize, ATT_SMEM);
        init = true;
    }

    // 1. conv_split(hidden) || transpose+split W_qkv
    pre_kernel<<<PRE_CTAS, 256>>>(
        (const float4*)hidden, (__nv_bfloat162*)ah_p, (__nv_bfloat162*)al_p, W_qkv);

    // 2. QKV GEMM + side work
    qkv_fused_kernel<<<QKV_GEMM_CTAS + NSIDE, 256, G_SMEM>>>(
        ah_p, al_p, wqh_p, wql_p, b_qkv, qkv_p,
        cached_k, cached_a, out_fk, out_na, W_dense);

    // 3. RoPE
    rope_kernel<<<(BATCH * NHEADS * SEQ * HDIM) / 256, 256>>>(out_fk);

    // 4. V transpose, new half only
    vtrans_new_kernel<<<dim3(SEQ / 32, HDIM / 32, BATCH * NHEADS), dim3(32, 8)>>>();

    // 5. tensor-core attention (cp.async double-buffered KV, LPT order)
    attn_mma_kernel<<<dim3(SEQ / 64, BATCH * NHEADS), 256, ATT_SMEM>>>(out_na);

    // 6. dense projection
    gemm_mma_split_kernel<<<dim3(HIDDEN / 128, MTOK / 128), 256, G_SMEM>>>(
        xh_p, xl_p, wdh_p, wdl_p, b_dense, out_main, MTOK, HIDDEN, HIDDEN);
}